// round 15
// baseline (speedup 1.0000x reference)
#include <cuda_runtime.h>
#include <math.h>

#define NB 16
#define NC 256
#define NN 4096
#define NK 8
#define HALF_OUT (NB*NC*NN)

typedef unsigned long long u64;

// ---------------- device scratch ----------------
__device__ float  d_gate  [2*NB*NN];
__device__ float  d_ag    [2*NB*NK*NN];
__device__ float  d_s     [2*NB*NK];
__device__ float  d_S2    [2*NB*NK*NK];
__device__ float  d_wxp   [8*2*NB*NK*NC];     // per-512px-chunk partial wx
__device__ float  d_sS2p  [2*NB*8*44];        // per-chunk partial s/S2
__device__ float  d_gflat [2*NB*NK*NC];
__device__ float  d_y4    [4*NB*NC*NK];
__device__ float  d_yrawp [4*4*NC*NB*NK];     // per-ichunk partial conv outputs [chunk][conv][o][b][k]
__device__ float  d_ce    [2*NB*NC*NK];
__device__ float2 d_pre   [2*NK*NC];
__device__ float  d_ck    [2*NK];
__device__ float  d_cwT   [2*NC*NC];
__device__ float4 d_wP4   [4*64*256];         // packed graph-conv weights: [conv][i/4][o] = W[o][4i..4i+3]
__device__ float  d_mpart [2*NB*NC];
__device__ float  d_vpart [2*NB*NC];

// ---------------- helpers ----------------
__device__ __forceinline__ float sigmoidf_(float x){ return 1.f/(1.f+expf(-x)); }

__device__ __forceinline__ u64 pack2(float x, float y){
  u64 r; asm("mov.b64 %0,{%1,%2};" : "=l"(r) : "f"(x), "f"(y)); return r;
}
__device__ __forceinline__ void unpack2(u64 v, float& x, float& y){
  asm("mov.b64 {%0,%1},%2;" : "=f"(x), "=f"(y) : "l"(v));
}
__device__ __forceinline__ u64 ffma2(u64 a, u64 b, u64 c){
  u64 d; asm("fma.rn.f32x2 %0,%1,%2,%3;" : "=l"(d) : "l"(a), "l"(b), "l"(c)); return d;
}

__device__ __forceinline__ float warpSum(float v){
  #pragma unroll
  for(int o=16;o>0;o>>=1) v += __shfl_xor_sync(0xffffffffu, v, o);
  return v;
}
__device__ float blockSum(float v, float* scratch){
  int lane = threadIdx.x & 31, w = threadIdx.x >> 5;
  int nw = blockDim.x >> 5;
  v = warpSum(v);
  if(lane==0) scratch[w]=v;
  __syncthreads();
  float r = (threadIdx.x < nw) ? scratch[threadIdx.x] : 0.f;
  if(w==0) r = warpSum(r);
  if(threadIdx.x==0) scratch[0]=r;
  __syncthreads();
  r = scratch[0];
  __syncthreads();
  return r;
}

// ---------------- kI: anchor coeffs + cw transpose + graph-conv W packing ----------------
__global__ void kI(const float* rgb_anchor, const float* rgb_sigma,
                   const float* t_anchor,  const float* t_sigma,
                   const float* t2r_w, const float* r2t_w,
                   const float* w0, const float* w1, const float* w2, const float* w3){
  int bid = blockIdx.x, t = threadIdx.x;
  if(bid < 16){
    int s = bid>>3, k = bid&7;
    const float* anc = s ? t_anchor : rgb_anchor;
    const float* sig = s ? t_sigma  : rgb_sigma;
    float sg  = sigmoidf_(sig[k*NC+t]);
    float is2 = 1.f/(sg*sg);
    float a   = anc[k*NC+t];
    d_pre[(s*NK+k)*NC+t] = make_float2(is2, 2.f*a*is2);
    __shared__ float sc[8];
    float ck = blockSum(a*a*is2, sc);
    if(t==0) d_ck[s*NK+k] = ck;
  } else if(bid < 528){
    int r = bid-16, s = r>>8, o = r&255;
    const float* w = s ? r2t_w : t2r_w;
    d_cwT[(size_t)s*NC*NC + t*NC + o] = w[o*NC + t];
  } else {
    int r = bid-528;                  // 0..255
    int conv = r>>6, i4 = r&63;
    const float* w = (conv==0)?w0 : (conv==1)?w1 : (conv==2)?w2 : w3;
    int o = t;
    d_wP4[((size_t)conv*64 + i4)*256 + o] = make_float4(
        w[o*NC + 4*i4], w[o*NC + 4*i4 + 1], w[o*NC + 4*i4 + 2], w[o*NC + 4*i4 + 3]);
  }
}

// ---------------- kBC: gate + q + softmax + wx partials (fused, f32x2-packed) ----------------
__global__ void __launch_bounds__(256) kBC(const float* rgb, const float* tt,
      const float* edger, const float* edget, const float* pred_w, const float* pred_b){
  int chunk = blockIdx.x, b = blockIdx.y, s = blockIdx.z;
  int t = threadIdx.x;
  __shared__ u64 agsp[4][512];                 // packed (k-pair) assign*gate, 16 KB
  __shared__ __align__(16) char ubuf[18432];   // predup (16K) then red (18.4K)
  __shared__ float pw[NC];
  __shared__ float cks[NK];
  __shared__ float part[44][8];
  ulonglong2 (*predup)[256] = (ulonglong2(*)[256])ubuf;
  float (*red)[8][9] = (float(*)[8][9])ubuf;

  pw[t] = pred_w[t];
  for(int idx=t; idx<4*NC; idx+=256){
    int kp = idx >> 8, c = idx & 255;
    float2 pa = d_pre[s*2048 + (2*kp  )*NC + c];
    float2 pb = d_pre[s*2048 + (2*kp+1)*NC + c];
    ulonglong2 v;
    v.x = pack2(pa.x, pb.x);
    v.y = pack2(-pa.y, -pb.y);
    predup[kp][c] = v;
  }
  if(t<NK) cks[t] = d_ck[s*NK+t];
  __syncthreads();

  int n0 = chunk*512;
  const float* ep = (s ? edget : edger) + (size_t)b*NC*NN + n0;
  const float* xp = (s ? tt    : rgb  ) + (size_t)b*NC*NN + n0;

  // ---- gate ----
  u64 gaA = pack2(0.f,0.f), gaB = pack2(0.f,0.f);
  {
    const float2* ep2 = (const float2*)ep;
    #pragma unroll 4
    for(int c=0;c<NC;c+=2){
      float2 e0 = ep2[(size_t)(c  )*(NN/2) + t];
      float2 e1 = ep2[(size_t)(c+1)*(NN/2) + t];
      gaA = ffma2(pack2(pw[c],pw[c]),     pack2(e0.x,e0.y), gaA);
      gaB = ffma2(pack2(pw[c+1],pw[c+1]), pack2(e1.x,e1.y), gaB);
    }
  }
  float ga0,ga1, gb0,gb1;
  unpack2(gaA,ga0,ga1); unpack2(gaB,gb0,gb1);
  float pb = pred_b[0];
  float g0 = sigmoidf_(ga0+gb0+pb), g1 = sigmoidf_(ga1+gb1+pb);

  // ---- q distances ----
  u64 qaS[4], qaL[4], qbS[4], qbL[4];
  #pragma unroll
  for(int kp=0;kp<4;kp++){
    qaS[kp]=pack2(cks[2*kp],cks[2*kp+1]); qbS[kp]=qaS[kp];
    qaL[kp]=pack2(0.f,0.f); qbL[kp]=pack2(0.f,0.f);
  }
  {
    const float2* xp2 = (const float2*)xp;
    #pragma unroll 4
    for(int c=0;c<NC;c++){
      float2 xv = xp2[(size_t)c*(NN/2)+t];
      float x0 = xv.x*g0, x1 = xv.y*g1;
      float x0s = x0*x0,  x1s = x1*x1;
      u64 X0 = pack2(x0,x0),   X1 = pack2(x1,x1);
      u64 X0s= pack2(x0s,x0s), X1s= pack2(x1s,x1s);
      #pragma unroll
      for(int kp=0;kp<4;kp++){
        ulonglong2 pd = predup[kp][c];
        qaS[kp] = ffma2(X0s, pd.x, qaS[kp]);
        qaL[kp] = ffma2(X0,  pd.y, qaL[kp]);
        qbS[kp] = ffma2(X1s, pd.x, qbS[kp]);
        qbL[kp] = ffma2(X1,  pd.y, qbL[kp]);
      }
    }
  }
  float q0[NK], q1[NK];
  #pragma unroll
  for(int kp=0;kp<4;kp++){
    float sA,sB,lA,lB;
    unpack2(qaS[kp],sA,sB); unpack2(qaL[kp],lA,lB);
    q0[2*kp]=sA+lA; q0[2*kp+1]=sB+lB;
    unpack2(qbS[kp],sA,sB); unpack2(qbL[kp],lA,lB);
    q1[2*kp]=sA+lA; q1[2*kp+1]=sB+lB;
  }

  // ---- softmax ----
  float a0[NK], a1[NK];
  {
    float mx0=-0.5f*q0[0], mx1=-0.5f*q1[0];
    #pragma unroll
    for(int k=1;k<NK;k++){ mx0=fmaxf(mx0,-0.5f*q0[k]); mx1=fmaxf(mx1,-0.5f*q1[k]); }
    float s0=0.f, s1=0.f;
    #pragma unroll
    for(int k=0;k<NK;k++){
      a0[k]=expf(-0.5f*q0[k]-mx0); s0+=a0[k];
      a1[k]=expf(-0.5f*q1[k]-mx1); s1+=a1[k];
    }
    float i0=1.f/s0, i1=1.f/s1;
    #pragma unroll
    for(int k=0;k<NK;k++){ a0[k]*=i0; a1[k]*=i1; }
  }
  // ---- write ag + gate; stage packed agsp ----
  {
    float a0g[NK], a1g[NK];
    #pragma unroll
    for(int k=0;k<NK;k++){ a0g[k]=a0[k]*g0; a1g[k]=a1[k]*g1; }
    float* agp = d_ag + (size_t)(s*NB+b)*NK*NN + n0;
    #pragma unroll
    for(int k=0;k<NK;k++)
      ((float2*)(agp + (size_t)k*NN))[t] = make_float2(a0g[k], a1g[k]);
    ((float2*)(d_gate + (size_t)(s*NB+b)*NN + n0))[t] = make_float2(g0, g1);
    #pragma unroll
    for(int kp=0;kp<4;kp++){
      ulonglong2 v;
      v.x = pack2(a0g[2*kp], a0g[2*kp+1]);
      v.y = pack2(a1g[2*kp], a1g[2*kp+1]);
      ((ulonglong2*)agsp[kp])[t] = v;
    }
  }
  // ---- s/S2 partials ----
  {
    int lane = t&31, w = t>>5;
    #pragma unroll
    for(int k=0;k<NK;k++){
      float v = warpSum(a0[k]+a1[k]);
      if(lane==0) part[k][w]=v;
    }
    int idx=8;
    #pragma unroll
    for(int k=0;k<NK;k++)
      #pragma unroll
      for(int l=k;l<NK;l++){
        float v = warpSum(a0[k]*a0[l] + a1[k]*a1[l]);
        if(lane==0) part[idx][w]=v;
        idx++;
      }
  }
  __syncthreads();
  if(t<44){
    float sv=0.f;
    #pragma unroll
    for(int p=0;p<8;p++) sv += part[t][p];
    d_sS2p[((s*NB+b)*8+chunk)*44 + t] = sv;
  }

  // ---- phase 2: wx partials from L2-resident x ----
  int cl = t>>3, nsub = t&7;
  for(int cg=0; cg<4; cg++){
    int c0 = cg*64 + cl, c1 = c0 + 32;
    const float4* x0p = (const float4*)(xp + (size_t)c0*NN);
    const float4* x1p = (const float4*)(xp + (size_t)c1*NN);
    u64 acc0[4], acc1[4];
    #pragma unroll
    for(int kp=0;kp<4;kp++){ acc0[kp]=pack2(0.f,0.f); acc1[kp]=acc0[kp]; }
    #pragma unroll 4
    for(int i=0;i<16;i++){
      int j = nsub + i*8;
      float4 xv0 = x0p[j];
      float4 xv1 = x1p[j];
      u64 P0x=pack2(xv0.x,xv0.x), P0y=pack2(xv0.y,xv0.y), P0z=pack2(xv0.z,xv0.z), P0w=pack2(xv0.w,xv0.w);
      u64 P1x=pack2(xv1.x,xv1.x), P1y=pack2(xv1.y,xv1.y), P1z=pack2(xv1.z,xv1.z), P1w=pack2(xv1.w,xv1.w);
      #pragma unroll
      for(int kp=0;kp<4;kp++){
        ulonglong2 apA = ((ulonglong2*)agsp[kp])[2*j];
        ulonglong2 apB = ((ulonglong2*)agsp[kp])[2*j+1];
        acc0[kp] = ffma2(P0x, apA.x, acc0[kp]);
        acc0[kp] = ffma2(P0y, apA.y, acc0[kp]);
        acc0[kp] = ffma2(P0z, apB.x, acc0[kp]);
        acc0[kp] = ffma2(P0w, apB.y, acc0[kp]);
        acc1[kp] = ffma2(P1x, apA.x, acc1[kp]);
        acc1[kp] = ffma2(P1y, apA.y, acc1[kp]);
        acc1[kp] = ffma2(P1z, apB.x, acc1[kp]);
        acc1[kp] = ffma2(P1w, apB.y, acc1[kp]);
      }
    }
    __syncthreads();
    #pragma unroll
    for(int kp=0;kp<4;kp++){
      float r0,r1;
      unpack2(acc0[kp],r0,r1); red[cl][nsub][2*kp]=r0; red[cl][nsub][2*kp+1]=r1;
      unpack2(acc1[kp],r0,r1); red[cl+32][nsub][2*kp]=r0; red[cl+32][nsub][2*kp+1]=r1;
    }
    __syncthreads();
    int cc = t>>3, k2 = t&7;
    float s0 = 0.f, s1 = 0.f;
    #pragma unroll
    for(int p=0;p<8;p++){ s0 += red[cc][p][k2]; s1 += red[cc+32][p][k2]; }
    float* wout = d_wxp + ((size_t)(chunk*(2*NB) + s*NB+b)*NK + k2)*NC + cg*64;
    wout[cc]    = s0;
    wout[cc+32] = s1;
  }
}

// ---------------- kD: reduce partials, nodes -> l2norms -> gflat ----------------
__global__ void __launch_bounds__(256) kD(const float* rgb_anchor, const float* rgb_sigma,
                   const float* t_anchor,  const float* t_sigma){
  int b = blockIdx.x, s = blockIdx.y, t = threadIdx.x;
  __shared__ float sc[8];
  __shared__ float s_sh[NK];
  __shared__ float part[NK][8];
  __shared__ float nks[NK];
  if(t<44){
    float sv=0.f;
    #pragma unroll
    for(int ch=0;ch<8;ch++) sv += d_sS2p[((s*NB+b)*8+ch)*44 + t];
    if(t<8){ d_s[(s*NB+b)*8 + t] = sv; s_sh[t] = sv; }
    else {
      int p=t-8, k=0;
      while(p >= NK-k){ p -= NK-k; k++; }
      int l = k+p;
      d_S2[(s*NB+b)*64 + k*8 + l] = sv;
      d_S2[(s*NB+b)*64 + l*8 + k] = sv;
    }
  }
  __syncthreads();
  const float* anc = s ? t_anchor : rgb_anchor;
  const float* sig = s ? t_sigma  : rgb_sigma;
  float val[NK];
  #pragma unroll
  for(int k=0;k<NK;k++){
    float wxv = 0.f;
    #pragma unroll
    for(int ch=0;ch<8;ch++)
      wxv += d_wxp[((size_t)(ch*(2*NB) + s*NB+b)*NK + k)*NC + t];
    float sv  = s_sh[k];
    float sg  = sigmoidf_(sig[k*NC+t]);
    val[k] = (wxv - sv*anc[k*NC+t]) / sg / (sv + 1e-9f);
  }
  int lane = t&31, w = t>>5;
  #pragma unroll
  for(int k=0;k<NK;k++){
    float v = warpSum(val[k]*val[k]);
    if(lane==0) part[k][w]=v;
  }
  __syncthreads();
  if(t<NK){
    float sv=0.f;
    #pragma unroll
    for(int p=0;p<8;p++) sv += part[t][p];
    nks[t] = fmaxf(sqrtf(sv), 1e-12f);
  }
  __syncthreads();
  float gss = 0.f;
  #pragma unroll
  for(int k=0;k<NK;k++){ val[k] = val[k]/nks[k]; gss += val[k]*val[k]; }
  float G = blockSum(gss, sc);
  float gn = fmaxf(sqrtf(G), 1e-12f);
  float* gf = d_gflat + (size_t)(s*NB+b)*2048;
  #pragma unroll
  for(int k=0;k<NK;k++) gf[k*NC+t] = val[k]/gn;
}

// ---------------- kE1: 4 graph convs, pre-BN, i-split into 4 chunks ----------------
// graph[b, i, k] = flat[i*NK + k]; flat IS gflat's memory layout
__global__ void __launch_bounds__(256) kE1(){
  int b = blockIdx.x, conv = blockIdx.y, ich = blockIdx.z;
  int t = threadIdx.x;
  int side = conv>>1;
  __shared__ __align__(16) float gfs[512];     // gflat slice for i in [ich*64, ich*64+64)
  {
    const float4* src = (const float4*)(d_gflat + (size_t)(side*NB+b)*2048 + ich*512);
    if(t<128) ((float4*)gfs)[t] = src[t];
  }
  __syncthreads();
  const float4* WP = d_wP4 + (size_t)conv*64*256 + (size_t)ich*16*256;
  u64 acc[4];
  #pragma unroll
  for(int kp=0;kp<4;kp++) acc[kp] = pack2(0.f,0.f);
  #pragma unroll
  for(int i4=0;i4<16;i4++){
    float4 w4 = WP[i4*256 + t];                       // W[o][...], coalesced LDG.128
    const ulonglong2* gp = ((const ulonglong2*)gfs) + i4*8;
    ulonglong2 gA = gp[0], gB = gp[1];
    ulonglong2 gC = gp[2], gD = gp[3];
    ulonglong2 gE = gp[4], gF = gp[5];
    ulonglong2 gG = gp[6], gH = gp[7];
    u64 W0=pack2(w4.x,w4.x), W1=pack2(w4.y,w4.y), W2=pack2(w4.z,w4.z), W3=pack2(w4.w,w4.w);
    acc[0]=ffma2(W0,gA.x,acc[0]); acc[1]=ffma2(W0,gA.y,acc[1]);
    acc[2]=ffma2(W0,gB.x,acc[2]); acc[3]=ffma2(W0,gB.y,acc[3]);
    acc[0]=ffma2(W1,gC.x,acc[0]); acc[1]=ffma2(W1,gC.y,acc[1]);
    acc[2]=ffma2(W1,gD.x,acc[2]); acc[3]=ffma2(W1,gD.y,acc[3]);
    acc[0]=ffma2(W2,gE.x,acc[0]); acc[1]=ffma2(W2,gE.y,acc[1]);
    acc[2]=ffma2(W2,gF.x,acc[2]); acc[3]=ffma2(W2,gF.y,acc[3]);
    acc[0]=ffma2(W3,gG.x,acc[0]); acc[1]=ffma2(W3,gG.y,acc[1]);
    acc[2]=ffma2(W3,gH.x,acc[2]); acc[3]=ffma2(W3,gH.y,acc[3]);
  }
  float a0,a1,a2,a3,a4,a5,a6,a7;
  unpack2(acc[0],a0,a1); unpack2(acc[1],a2,a3);
  unpack2(acc[2],a4,a5); unpack2(acc[3],a6,a7);
  float* yr = d_yrawp + (((size_t)(ich*4+conv)*NC + t)*NB + b)*NK;
  ((float4*)yr)[0] = make_float4(a0,a1,a2,a3);
  ((float4*)yr)[1] = make_float4(a4,a5,a6,a7);
}

// ---------------- kE2: sum i-chunk partials + BN(relu) over (B,K) per (conv,o) ----------------
__global__ void __launch_bounds__(128) kE2(
    const float* g0,const float* b0, const float* g1,const float* b1,
    const float* g2,const float* b2, const float* g3,const float* b3){
  int o = blockIdx.x, conv = blockIdx.y, t = threadIdx.x;
  const float *gg, *bb;
  if(conv==0){gg=g0;bb=b0;} else if(conv==1){gg=g1;bb=b1;}
  else if(conv==2){gg=g2;bb=b2;} else {gg=g3;bb=b3;}
  __shared__ float sc[8];
  float v = 0.f;
  #pragma unroll
  for(int ich=0;ich<4;ich++)
    v += d_yrawp[((size_t)(ich*4+conv)*NC + o)*NB*NK + t];
  float su = blockSum(v, sc);
  float sq = blockSum(v*v, sc);
  float mean = su*(1.f/128.f);
  float var  = sq*(1.f/128.f) - mean*mean;
  float y = gg[o]*(v-mean)*rsqrtf(var+1e-5f) + bb[o];
  int b = t>>3, k = t&7;
  d_y4[((size_t)(conv*NB+b)*NC + o)*NK + k] = fmaxf(y, 0.f);
}

// ---------------- kF: mutual correlation + 2x cascade GCN + conv fold + BN stats ----------------
__global__ void __launch_bounds__(256) kF(
    const float* t2r_g1, const float* t2r_g2, const float* r2t_g1, const float* r2t_g2){
  int b = blockIdx.x, s = blockIdx.y, t = threadIdx.x;
  const float* W1  = s ? r2t_g1 : t2r_g1;
  const float* W2  = s ? r2t_g2 : t2r_g2;
  const float* cwT = d_cwT + (size_t)s*NC*NC;
  int c1 = s ? 0 : 2;
  __shared__ __align__(16) float e[NC][NK], r1[NC][NK], r2[NC][NK], xa[NC][NK], xb[NC][NK];
  __shared__ float A[NK][NK+1];
  {
    const float* gf = d_gflat + (size_t)(s*NB+b)*2048;
    const float* y1 = d_y4 + (size_t)(c1*NB+b)*NC*NK;
    const float* y2 = d_y4 + (size_t)((c1+1)*NB+b)*NC*NK;
    // edge[c][k] = flat[c*NK + k] = gf[c*NK + k]  (contiguous -> float4 pair)
    float4 ea = ((const float4*)(gf + t*NK))[0], eb4 = ((const float4*)(gf + t*NK))[1];
    *(float4*)&e[t][0] = ea; *(float4*)&e[t][4] = eb4;
    float4 ya = ((const float4*)(y1 + t*NK))[0], yb4 = ((const float4*)(y1 + t*NK))[1];
    *(float4*)&r1[t][0] = ya; *(float4*)&r1[t][4] = yb4;
    float4 yc = ((const float4*)(y2 + t*NK))[0], yd = ((const float4*)(y2 + t*NK))[1];
    *(float4*)&r2[t][0] = yc; *(float4*)&r2[t][4] = yd;
  }
  __syncthreads();
  {
    int pair = t>>2, part = t&3;
    int k = pair>>3, l = pair&7;
    float acc=0.f;
    #pragma unroll 4
    for(int c=part;c<NC;c+=4) acc += e[c][k]*r1[c][l];
    acc += __shfl_down_sync(0xffffffffu, acc, 1);
    acc += __shfl_down_sync(0xffffffffu, acc, 2);
    if(part==0) A[k][l] = acc;
  }
  __syncthreads();
  if(t<NK){
    float mx=A[t][0];
    #pragma unroll
    for(int l=1;l<NK;l++) mx = fmaxf(mx, A[t][l]);
    float sm=0.f, ee[NK];
    #pragma unroll
    for(int l=0;l<NK;l++){ ee[l]=expf(A[t][l]-mx); sm+=ee[l]; }
    #pragma unroll
    for(int l=0;l<NK;l++) A[t][l] = ee[l]/sm;
  }
  __syncthreads();
  {
    float rr[NK];
    float4 ra = *(float4*)&r2[t][0], rb = *(float4*)&r2[t][4];
    rr[0]=ra.x; rr[1]=ra.y; rr[2]=ra.z; rr[3]=ra.w;
    rr[4]=rb.x; rr[5]=rb.y; rr[6]=rb.z; rr[7]=rb.w;
    #pragma unroll
    for(int k=0;k<NK;k++){
      float m=0.f;
      #pragma unroll
      for(int l=0;l<NK;l++) m += A[k][l]*rr[l];
      xa[t][k] = e[t][k] + m;
    }
  }
  __syncthreads();
  for(int it=0; it<2; it++){
    float (*xin)[NK]  = it ? xb : xa;
    float (*xout)[NK] = it ? xa : xb;
    const float* W = it ? W2 : W1;
    {
      int pair=t>>2, part=t&3, k=pair>>3, l=pair&7;
      float acc=0.f;
      #pragma unroll 4
      for(int c=part;c<NC;c+=4) acc += xin[c][k]*xin[c][l];
      acc += __shfl_down_sync(0xffffffffu, acc, 1);
      acc += __shfl_down_sync(0xffffffffu, acc, 2);
      if(part==0) A[k][l]=acc;
    }
    __syncthreads();
    if(t<NK){
      float mx=A[t][0];
      #pragma unroll
      for(int l=1;l<NK;l++) mx=fmaxf(mx,A[t][l]);
      float sm=0.f, ee[NK];
      #pragma unroll
      for(int l=0;l<NK;l++){ ee[l]=expf(A[t][l]-mx); sm+=ee[l]; }
      #pragma unroll
      for(int l=0;l<NK;l++) A[t][l]=ee[l]/sm;
    }
    __syncthreads();
    float acc[NK];
    #pragma unroll
    for(int l=0;l<NK;l++) acc[l]=0.f;
    #pragma unroll 8
    for(int i=0;i<NC;i++){
      float w = W[i*NC + t];
      float4 xA = *(float4*)&xin[i][0], xB = *(float4*)&xin[i][4];
      acc[0]+=xA.x*w; acc[1]+=xA.y*w; acc[2]+=xA.z*w; acc[3]+=xA.w*w;
      acc[4]+=xB.x*w; acc[5]+=xB.y*w; acc[6]+=xB.z*w; acc[7]+=xB.w*w;
    }
    bool last = (it==1);
    #pragma unroll
    for(int k=0;k<NK;k++){
      float v=0.f;
      #pragma unroll
      for(int l=0;l<NK;l++) v += A[k][l]*acc[l];
      xout[t][k] = last ? fmaxf(v,0.f) : v;
    }
    __syncthreads();
  }
  float ce[NK];
  #pragma unroll
  for(int k=0;k<NK;k++) ce[k]=0.f;
  #pragma unroll 8
  for(int i=0;i<NC;i++){
    float w = cwT[i*NC + t];
    float4 xA = *(float4*)&xa[i][0], xB = *(float4*)&xa[i][4];
    ce[0]+=xA.x*w; ce[1]+=xA.y*w; ce[2]+=xA.z*w; ce[3]+=xA.w*w;
    ce[4]+=xB.x*w; ce[5]+=xB.y*w; ce[6]+=xB.z*w; ce[7]+=xB.w*w;
  }
  const float* sb = d_s  + (s*NB+b)*NK;
  const float* S2 = d_S2 + (s*NB+b)*64;
  float mp=0.f, vp=0.f;
  #pragma unroll
  for(int k=0;k<NK;k++) mp += ce[k]*sb[k];
  #pragma unroll
  for(int k=0;k<NK;k++)
    #pragma unroll
    for(int l=0;l<NK;l++) vp += ce[k]*ce[l]*S2[k*8+l];
  d_mpart[(s*NB+b)*NC + t] = mp;
  d_vpart[(s*NB+b)*NC + t] = vp;
  float* cep = d_ce + ((size_t)(s*NB+b)*NC + t)*NK;
  ((float4*)cep)[0] = make_float4(ce[0],ce[1],ce[2],ce[3]);
  ((float4*)cep)[1] = make_float4(ce[4],ce[5],ce[6],ce[7]);
}

// ---------------- kH: BN-fold + out = gate*x + relu(alpha*((ce.ag)/g) + beta) ----------------
__global__ void __launch_bounds__(256) kH(const float* rgb, const float* tt, float* out,
      const float* t2r_g, const float* t2r_b, const float* r2t_g, const float* r2t_b){
  int chunk = blockIdx.x, b = blockIdx.y;
  int s = blockIdx.z >> 2, cq = blockIdx.z & 3;
  int t = threadIdx.x;
  __shared__ u64 cesd[64][NK];
  __shared__ float2 ab[64];
  int n0 = chunk*1024;
  if(t<64){
    int c = cq*64 + t;
    float ms=0.f, vs=0.f;
    #pragma unroll
    for(int b2=0;b2<NB;b2++){
      ms += d_mpart[(s*NB+b2)*NC + c];
      vs += d_vpart[(s*NB+b2)*NC + c];
    }
    float mean = ms * (1.f/65536.f);
    float var  = vs * (1.f/65536.f) - mean*mean;
    float gg = s ? r2t_g[c] : t2r_g[c];
    float bv = s ? r2t_b[c] : t2r_b[c];
    float al = gg*rsqrtf(var + 1e-5f);
    ab[t] = make_float2(al, bv - al*mean);
  }
  for(int idx=t; idx<64*NK; idx+=256){
    int cl = idx>>3, k = idx&7;
    float cv = d_ce[((size_t)(s*NB+b)*NC + cq*64+cl)*NK + k];
    cesd[cl][k] = pack2(cv, cv);
  }
  const float* agp = d_ag + (size_t)(s*NB+b)*NK*NN + n0;
  u64 avlo[NK], avhi[NK];
  float4 gv;
  {
    #pragma unroll
    for(int k=0;k<NK;k++){
      float4 a4 = ((const float4*)(agp + (size_t)k*NN))[t];
      avlo[k] = pack2(a4.x, a4.y);
      avhi[k] = pack2(a4.z, a4.w);
    }
    gv = ((const float4*)(d_gate + (size_t)(s*NB+b)*NN + n0))[t];
  }
  float4 ivg = make_float4(__frcp_rn(gv.x), __frcp_rn(gv.y), __frcp_rn(gv.z), __frcp_rn(gv.w));
  __syncthreads();
  const float* xp = (s ? tt : rgb) + (size_t)b*NC*NN + n0;
  float* op = out + (size_t)s*HALF_OUT + (size_t)b*NC*NN + n0;
  #pragma unroll 2
  for(int cl=0; cl<64; cl++){
    size_t coff = (size_t)(cq*64 + cl)*NN;
    float4 xv = ((const float4*)(xp + coff))[t];
    u64 p01 = pack2(0.f,0.f), p23 = pack2(0.f,0.f);
    #pragma unroll
    for(int k=0;k<NK;k++){
      u64 cd = cesd[cl][k];
      p01 = ffma2(avlo[k], cd, p01);
      p23 = ffma2(avhi[k], cd, p23);
    }
    float px_,py_,pz_,pw_;
    unpack2(p01,px_,py_); unpack2(p23,pz_,pw_);
    float2 abv = ab[cl];
    float4 o4;
    o4.x = gv.x*xv.x + fmaxf(abv.x*(px_*ivg.x) + abv.y, 0.f);
    o4.y = gv.y*xv.y + fmaxf(abv.x*(py_*ivg.y) + abv.y, 0.f);
    o4.z = gv.z*xv.z + fmaxf(abv.x*(pz_*ivg.z) + abv.y, 0.f);
    o4.w = gv.w*xv.w + fmaxf(abv.x*(pw_*ivg.w) + abv.y, 0.f);
    ((float4*)(op + coff))[t] = o4;
  }
}

// ---------------- launch ----------------
extern "C" void kernel_launch(void* const* d_in, const int* in_sizes, int n_in,
                              void* d_out, int out_size){
  (void)in_sizes; (void)n_in; (void)out_size;
  const float* rgb    = (const float*)d_in[0];
  const float* tt     = (const float*)d_in[1];
  const float* edger  = (const float*)d_in[2];
  const float* edget  = (const float*)d_in[3];
  const float* pred_w = (const float*)d_in[4];
  const float* pred_b = (const float*)d_in[5];
  const float* rgb_anchor=(const float*)d_in[6];
  const float* rgb_sigma =(const float*)d_in[7];
  const float* t_anchor  =(const float*)d_in[8];
  const float* t_sigma   =(const float*)d_in[9];
  const float* rgb_c1_w=(const float*)d_in[10]; const float* rgb_c1_g=(const float*)d_in[11]; const float* rgb_c1_b=(const float*)d_in[12];
  const float* rgb_c2_w=(const float*)d_in[13]; const float* rgb_c2_g=(const float*)d_in[14]; const float* rgb_c2_b=(const float*)d_in[15];
  const float* t_c1_w  =(const float*)d_in[16]; const float* t_c1_g  =(const float*)d_in[17]; const float* t_c1_b  =(const float*)d_in[18];
  const float* t_c2_w  =(const float*)d_in[19]; const float* t_c2_g  =(const float*)d_in[20]; const float* t_c2_b  =(const float*)d_in[21];
  const float* t2r_conv_w=(const float*)d_in[22]; const float* t2r_conv_g=(const float*)d_in[23]; const float* t2r_conv_b=(const float*)d_in[24];
  const float* r2t_conv_w=(const float*)d_in[25]; const float* r2t_conv_g=(const float*)d_in[26]; const float* r2t_conv_b=(const float*)d_in[27];
  const float* t2r_g1=(const float*)d_in[28]; const float* t2r_g2=(const float*)d_in[29];
  const float* r2t_g1=(const float*)d_in[30]; const float* r2t_g2=(const float*)d_in[31];
  float* out = (float*)d_out;

  kI <<<784, NC>>>(rgb_anchor, rgb_sigma, t_anchor, t_sigma, t2r_conv_w, r2t_conv_w,
                   rgb_c1_w, rgb_c2_w, t_c1_w, t_c2_w);
  kBC<<<dim3(8,NB,2), 256>>>(rgb, tt, edger, edget, pred_w, pred_b);
  kD <<<dim3(NB,2), 256>>>(rgb_anchor, rgb_sigma, t_anchor, t_sigma);
  kE1<<<dim3(NB,4,4), 256>>>();
  kE2<<<dim3(NC,4), 128>>>(rgb_c1_g,rgb_c1_b, rgb_c2_g,rgb_c2_b,
                           t_c1_g,t_c1_b, t_c2_g,t_c2_b);
  kF <<<dim3(NB,2), 256>>>(t2r_g1, t2r_g2, r2t_g1, r2t_g2);
  kH <<<dim3(4,NB,8), 256>>>(rgb, tt, out, t2r_conv_g, t2r_conv_b, r2t_conv_g, r2t_conv_b);
}

// round 16
// speedup vs baseline: 1.1986x; 1.1986x over previous
#include <cuda_runtime.h>
#include <math.h>

#define NB 16
#define NC 256
#define NN 4096
#define NK 8
#define HALF_OUT (NB*NC*NN)

typedef unsigned long long u64;

// ---------------- device scratch ----------------
__device__ float  d_gate  [2*NB*NN];
__device__ float  d_ag    [2*NB*NK*NN];
__device__ float  d_s     [2*NB*NK];
__device__ float  d_S2    [2*NB*NK*NK];
__device__ float  d_wxp   [16*2*NB*NK*NC];    // per-256px-chunk partial wx
__device__ float  d_sS2p  [2*NB*16*44];       // per-chunk partial s/S2
__device__ float  d_gflat [2*NB*NK*NC];
__device__ float  d_y4    [4*NB*NC*NK];
__device__ float  d_yrawp [4*4*NC*NB*NK];     // per-ichunk partial conv outputs
__device__ float  d_ce    [2*NB*NC*NK];
__device__ float2 d_pre   [2*NK*NC];
__device__ float  d_ck    [2*NK];
__device__ float  d_cwT   [2*NC*NC];
__device__ float4 d_wP4   [4*64*256];         // packed graph-conv weights
__device__ float  d_mpart [2*NB*NC];
__device__ float  d_vpart [2*NB*NC];

// ---------------- helpers ----------------
__device__ __forceinline__ float sigmoidf_(float x){ return 1.f/(1.f+expf(-x)); }

__device__ __forceinline__ u64 pack2(float x, float y){
  u64 r; asm("mov.b64 %0,{%1,%2};" : "=l"(r) : "f"(x), "f"(y)); return r;
}
__device__ __forceinline__ void unpack2(u64 v, float& x, float& y){
  asm("mov.b64 {%0,%1},%2;" : "=f"(x), "=f"(y) : "l"(v));
}
__device__ __forceinline__ u64 ffma2(u64 a, u64 b, u64 c){
  u64 d; asm("fma.rn.f32x2 %0,%1,%2,%3;" : "=l"(d) : "l"(a), "l"(b), "l"(c)); return d;
}

__device__ __forceinline__ float warpSum(float v){
  #pragma unroll
  for(int o=16;o>0;o>>=1) v += __shfl_xor_sync(0xffffffffu, v, o);
  return v;
}
__device__ float blockSum(float v, float* scratch){
  int lane = threadIdx.x & 31, w = threadIdx.x >> 5;
  int nw = blockDim.x >> 5;
  v = warpSum(v);
  if(lane==0) scratch[w]=v;
  __syncthreads();
  float r = (threadIdx.x < nw) ? scratch[threadIdx.x] : 0.f;
  if(w==0) r = warpSum(r);
  if(threadIdx.x==0) scratch[0]=r;
  __syncthreads();
  r = scratch[0];
  __syncthreads();
  return r;
}

// ---------------- kI: anchor coeffs + cw transpose + graph-conv W packing ----------------
__global__ void kI(const float* rgb_anchor, const float* rgb_sigma,
                   const float* t_anchor,  const float* t_sigma,
                   const float* t2r_w, const float* r2t_w,
                   const float* w0, const float* w1, const float* w2, const float* w3){
  int bid = blockIdx.x, t = threadIdx.x;
  if(bid < 16){
    int s = bid>>3, k = bid&7;
    const float* anc = s ? t_anchor : rgb_anchor;
    const float* sig = s ? t_sigma  : rgb_sigma;
    float sg  = sigmoidf_(sig[k*NC+t]);
    float is2 = 1.f/(sg*sg);
    float a   = anc[k*NC+t];
    d_pre[(s*NK+k)*NC+t] = make_float2(is2, 2.f*a*is2);
    __shared__ float sc[8];
    float ck = blockSum(a*a*is2, sc);
    if(t==0) d_ck[s*NK+k] = ck;
  } else if(bid < 528){
    int r = bid-16, s = r>>8, o = r&255;
    const float* w = s ? r2t_w : t2r_w;
    d_cwT[(size_t)s*NC*NC + t*NC + o] = w[o*NC + t];
  } else {
    int r = bid-528;                  // 0..255
    int conv = r>>6, i4 = r&63;
    const float* w = (conv==0)?w0 : (conv==1)?w1 : (conv==2)?w2 : w3;
    int o = t;
    d_wP4[((size_t)conv*64 + i4)*256 + o] = make_float4(
        w[o*NC + 4*i4], w[o*NC + 4*i4 + 1], w[o*NC + 4*i4 + 2], w[o*NC + 4*i4 + 3]);
  }
}

// ---------------- kBC: gate + q + softmax + wx partials (128 thr, 256-px chunks) ----------------
__global__ void __launch_bounds__(128) kBC(const float* rgb, const float* tt,
      const float* edger, const float* edget, const float* pred_w, const float* pred_b){
  int chunk = blockIdx.x, b = blockIdx.y, s = blockIdx.z;
  int t = threadIdx.x;                          // 0..127
  __shared__ u64 agsp[4][256];                  // packed (k-pair) assign*gate, px-major, 8 KB
  __shared__ __align__(16) char ubuf[16384];    // predup (16K) then red (9.2K)
  __shared__ float pw[NC];
  __shared__ float cks[NK];
  __shared__ float part[44][4];
  ulonglong2 (*predup)[256] = (ulonglong2(*)[256])ubuf;
  float (*red)[4][9] = (float(*)[4][9])ubuf;    // [64][4][9]

  pw[t] = pred_w[t]; pw[t+128] = pred_w[t+128];
  for(int idx=t; idx<4*NC; idx+=128){
    int kp = idx >> 8, c = idx & 255;
    float2 pa = d_pre[s*2048 + (2*kp  )*NC + c];
    float2 pb = d_pre[s*2048 + (2*kp+1)*NC + c];
    ulonglong2 v;
    v.x = pack2(pa.x, pb.x);
    v.y = pack2(-pa.y, -pb.y);
    predup[kp][c] = v;
  }
  if(t<NK) cks[t] = d_ck[s*NK+t];
  __syncthreads();

  int n0 = chunk*256;
  const float* ep = (s ? edget : edger) + (size_t)b*NC*NN + n0;
  const float* xp = (s ? tt    : rgb  ) + (size_t)b*NC*NN + n0;

  // ---- gate ----
  u64 gaA = pack2(0.f,0.f), gaB = pack2(0.f,0.f);
  {
    const float2* ep2 = (const float2*)ep;
    #pragma unroll 4
    for(int c=0;c<NC;c+=2){
      float2 e0 = ep2[(size_t)(c  )*(NN/2) + t];
      float2 e1 = ep2[(size_t)(c+1)*(NN/2) + t];
      gaA = ffma2(pack2(pw[c],pw[c]),     pack2(e0.x,e0.y), gaA);
      gaB = ffma2(pack2(pw[c+1],pw[c+1]), pack2(e1.x,e1.y), gaB);
    }
  }
  float ga0,ga1, gb0,gb1;
  unpack2(gaA,ga0,ga1); unpack2(gaB,gb0,gb1);
  float pb = pred_b[0];
  float g0 = sigmoidf_(ga0+gb0+pb), g1 = sigmoidf_(ga1+gb1+pb);

  // ---- q distances ----
  u64 qaS[4], qaL[4], qbS[4], qbL[4];
  #pragma unroll
  for(int kp=0;kp<4;kp++){
    qaS[kp]=pack2(cks[2*kp],cks[2*kp+1]); qbS[kp]=qaS[kp];
    qaL[kp]=pack2(0.f,0.f); qbL[kp]=pack2(0.f,0.f);
  }
  {
    const float2* xp2 = (const float2*)xp;
    #pragma unroll 4
    for(int c=0;c<NC;c++){
      float2 xv = xp2[(size_t)c*(NN/2)+t];
      float x0 = xv.x*g0, x1 = xv.y*g1;
      float x0s = x0*x0,  x1s = x1*x1;
      u64 X0 = pack2(x0,x0),   X1 = pack2(x1,x1);
      u64 X0s= pack2(x0s,x0s), X1s= pack2(x1s,x1s);
      #pragma unroll
      for(int kp=0;kp<4;kp++){
        ulonglong2 pd = predup[kp][c];
        qaS[kp] = ffma2(X0s, pd.x, qaS[kp]);
        qaL[kp] = ffma2(X0,  pd.y, qaL[kp]);
        qbS[kp] = ffma2(X1s, pd.x, qbS[kp]);
        qbL[kp] = ffma2(X1,  pd.y, qbL[kp]);
      }
    }
  }
  float q0[NK], q1[NK];
  #pragma unroll
  for(int kp=0;kp<4;kp++){
    float sA,sB,lA,lB;
    unpack2(qaS[kp],sA,sB); unpack2(qaL[kp],lA,lB);
    q0[2*kp]=sA+lA; q0[2*kp+1]=sB+lB;
    unpack2(qbS[kp],sA,sB); unpack2(qbL[kp],lA,lB);
    q1[2*kp]=sA+lA; q1[2*kp+1]=sB+lB;
  }

  // ---- softmax ----
  float a0[NK], a1[NK];
  {
    float mx0=-0.5f*q0[0], mx1=-0.5f*q1[0];
    #pragma unroll
    for(int k=1;k<NK;k++){ mx0=fmaxf(mx0,-0.5f*q0[k]); mx1=fmaxf(mx1,-0.5f*q1[k]); }
    float s0=0.f, s1=0.f;
    #pragma unroll
    for(int k=0;k<NK;k++){
      a0[k]=expf(-0.5f*q0[k]-mx0); s0+=a0[k];
      a1[k]=expf(-0.5f*q1[k]-mx1); s1+=a1[k];
    }
    float i0=1.f/s0, i1=1.f/s1;
    #pragma unroll
    for(int k=0;k<NK;k++){ a0[k]*=i0; a1[k]*=i1; }
  }
  // ---- write ag + gate; stage packed agsp (px 2t, 2t+1) ----
  {
    float a0g[NK], a1g[NK];
    #pragma unroll
    for(int k=0;k<NK;k++){ a0g[k]=a0[k]*g0; a1g[k]=a1[k]*g1; }
    float* agp = d_ag + (size_t)(s*NB+b)*NK*NN + n0;
    #pragma unroll
    for(int k=0;k<NK;k++)
      ((float2*)(agp + (size_t)k*NN))[t] = make_float2(a0g[k], a1g[k]);
    ((float2*)(d_gate + (size_t)(s*NB+b)*NN + n0))[t] = make_float2(g0, g1);
    #pragma unroll
    for(int kp=0;kp<4;kp++){
      ulonglong2 v;
      v.x = pack2(a0g[2*kp], a0g[2*kp+1]);    // pixel 2t
      v.y = pack2(a1g[2*kp], a1g[2*kp+1]);    // pixel 2t+1
      ((ulonglong2*)agsp[kp])[t] = v;
    }
  }
  // ---- s/S2 partials ----
  {
    int lane = t&31, w = t>>5;
    #pragma unroll
    for(int k=0;k<NK;k++){
      float v = warpSum(a0[k]+a1[k]);
      if(lane==0) part[k][w]=v;
    }
    int idx=8;
    #pragma unroll
    for(int k=0;k<NK;k++)
      #pragma unroll
      for(int l=k;l<NK;l++){
        float v = warpSum(a0[k]*a0[l] + a1[k]*a1[l]);
        if(lane==0) part[idx][w]=v;
        idx++;
      }
  }
  __syncthreads();
  if(t<44){
    float sv=0.f;
    #pragma unroll
    for(int p=0;p<4;p++) sv += part[t][p];
    d_sS2p[((s*NB+b)*16+chunk)*44 + t] = sv;
  }

  // ---- phase 2: wx partials from L2-resident x ----
  int cl = t>>2, nsub = t&3;                    // cl: 0..31, nsub: 0..3
  for(int cg=0; cg<4; cg++){
    int c0 = cg*64 + cl, c1 = c0 + 32;
    const float4* x0p = (const float4*)(xp + (size_t)c0*NN);
    const float4* x1p = (const float4*)(xp + (size_t)c1*NN);
    u64 acc0[4], acc1[4];
    #pragma unroll
    for(int kp=0;kp<4;kp++){ acc0[kp]=pack2(0.f,0.f); acc1[kp]=acc0[kp]; }
    #pragma unroll 4
    for(int i=0;i<16;i++){
      int j = nsub + i*4;                       // j < 64 (256px / 4)
      float4 xv0 = x0p[j];
      float4 xv1 = x1p[j];
      u64 P0x=pack2(xv0.x,xv0.x), P0y=pack2(xv0.y,xv0.y), P0z=pack2(xv0.z,xv0.z), P0w=pack2(xv0.w,xv0.w);
      u64 P1x=pack2(xv1.x,xv1.x), P1y=pack2(xv1.y,xv1.y), P1z=pack2(xv1.z,xv1.z), P1w=pack2(xv1.w,xv1.w);
      #pragma unroll
      for(int kp=0;kp<4;kp++){
        ulonglong2 apA = ((ulonglong2*)agsp[kp])[2*j];     // px 4j, 4j+1
        ulonglong2 apB = ((ulonglong2*)agsp[kp])[2*j+1];   // px 4j+2, 4j+3
        acc0[kp] = ffma2(P0x, apA.x, acc0[kp]);
        acc0[kp] = ffma2(P0y, apA.y, acc0[kp]);
        acc0[kp] = ffma2(P0z, apB.x, acc0[kp]);
        acc0[kp] = ffma2(P0w, apB.y, acc0[kp]);
        acc1[kp] = ffma2(P1x, apA.x, acc1[kp]);
        acc1[kp] = ffma2(P1y, apA.y, acc1[kp]);
        acc1[kp] = ffma2(P1z, apB.x, acc1[kp]);
        acc1[kp] = ffma2(P1w, apB.y, acc1[kp]);
      }
    }
    __syncthreads();
    #pragma unroll
    for(int kp=0;kp<4;kp++){
      float r0,r1;
      unpack2(acc0[kp],r0,r1); red[cl][nsub][2*kp]=r0; red[cl][nsub][2*kp+1]=r1;
      unpack2(acc1[kp],r0,r1); red[cl+32][nsub][2*kp]=r0; red[cl+32][nsub][2*kp+1]=r1;
    }
    __syncthreads();
    float* wout = d_wxp + ((size_t)(chunk*(2*NB) + s*NB+b))*NK*NC;
    for(int r=t; r<512; r+=128){
      int cc = r>>3, k2 = r&7;
      float sum = 0.f;
      #pragma unroll
      for(int p=0;p<4;p++) sum += red[cc][p][k2];
      wout[(size_t)k2*NC + cg*64 + cc] = sum;
    }
    __syncthreads();
  }
}

// ---------------- kD: reduce partials, nodes -> l2norms -> gflat ----------------
__global__ void __launch_bounds__(256) kD(const float* rgb_anchor, const float* rgb_sigma,
                   const float* t_anchor,  const float* t_sigma){
  int b = blockIdx.x, s = blockIdx.y, t = threadIdx.x;
  __shared__ float sc[8];
  __shared__ float s_sh[NK];
  __shared__ float part[NK][8];
  __shared__ float nks[NK];
  if(t<44){
    float sv=0.f;
    #pragma unroll
    for(int ch=0;ch<16;ch++) sv += d_sS2p[((s*NB+b)*16+ch)*44 + t];
    if(t<8){ d_s[(s*NB+b)*8 + t] = sv; s_sh[t] = sv; }
    else {
      int p=t-8, k=0;
      while(p >= NK-k){ p -= NK-k; k++; }
      int l = k+p;
      d_S2[(s*NB+b)*64 + k*8 + l] = sv;
      d_S2[(s*NB+b)*64 + l*8 + k] = sv;
    }
  }
  __syncthreads();
  const float* anc = s ? t_anchor : rgb_anchor;
  const float* sig = s ? t_sigma  : rgb_sigma;
  float val[NK];
  #pragma unroll
  for(int k=0;k<NK;k++){
    float wxv = 0.f;
    #pragma unroll
    for(int ch=0;ch<16;ch++)
      wxv += d_wxp[((size_t)(ch*(2*NB) + s*NB+b)*NK + k)*NC + t];
    float sv  = s_sh[k];
    float sg  = sigmoidf_(sig[k*NC+t]);
    val[k] = (wxv - sv*anc[k*NC+t]) / sg / (sv + 1e-9f);
  }
  int lane = t&31, w = t>>5;
  #pragma unroll
  for(int k=0;k<NK;k++){
    float v = warpSum(val[k]*val[k]);
    if(lane==0) part[k][w]=v;
  }
  __syncthreads();
  if(t<NK){
    float sv=0.f;
    #pragma unroll
    for(int p=0;p<8;p++) sv += part[t][p];
    nks[t] = fmaxf(sqrtf(sv), 1e-12f);
  }
  __syncthreads();
  float gss = 0.f;
  #pragma unroll
  for(int k=0;k<NK;k++){ val[k] = val[k]/nks[k]; gss += val[k]*val[k]; }
  float G = blockSum(gss, sc);
  float gn = fmaxf(sqrtf(G), 1e-12f);
  float* gf = d_gflat + (size_t)(s*NB+b)*2048;
  #pragma unroll
  for(int k=0;k<NK;k++) gf[k*NC+t] = val[k]/gn;
}

// ---------------- kE1: 4 graph convs, pre-BN, i-split into 4 chunks ----------------
__global__ void __launch_bounds__(256) kE1(){
  int b = blockIdx.x, conv = blockIdx.y, ich = blockIdx.z;
  int t = threadIdx.x;
  int side = conv>>1;
  __shared__ __align__(16) float gfs[512];
  {
    const float4* src = (const float4*)(d_gflat + (size_t)(side*NB+b)*2048 + ich*512);
    if(t<128) ((float4*)gfs)[t] = src[t];
  }
  __syncthreads();
  const float4* WP = d_wP4 + (size_t)conv*64*256 + (size_t)ich*16*256;
  u64 acc[4];
  #pragma unroll
  for(int kp=0;kp<4;kp++) acc[kp] = pack2(0.f,0.f);
  #pragma unroll
  for(int i4=0;i4<16;i4++){
    float4 w4 = WP[i4*256 + t];
    const ulonglong2* gp = ((const ulonglong2*)gfs) + i4*8;
    ulonglong2 gA = gp[0], gB = gp[1];
    ulonglong2 gC = gp[2], gD = gp[3];
    ulonglong2 gE = gp[4], gF = gp[5];
    ulonglong2 gG = gp[6], gH = gp[7];
    u64 W0=pack2(w4.x,w4.x), W1=pack2(w4.y,w4.y), W2=pack2(w4.z,w4.z), W3=pack2(w4.w,w4.w);
    acc[0]=ffma2(W0,gA.x,acc[0]); acc[1]=ffma2(W0,gA.y,acc[1]);
    acc[2]=ffma2(W0,gB.x,acc[2]); acc[3]=ffma2(W0,gB.y,acc[3]);
    acc[0]=ffma2(W1,gC.x,acc[0]); acc[1]=ffma2(W1,gC.y,acc[1]);
    acc[2]=ffma2(W1,gD.x,acc[2]); acc[3]=ffma2(W1,gD.y,acc[3]);
    acc[0]=ffma2(W2,gE.x,acc[0]); acc[1]=ffma2(W2,gE.y,acc[1]);
    acc[2]=ffma2(W2,gF.x,acc[2]); acc[3]=ffma2(W2,gF.y,acc[3]);
    acc[0]=ffma2(W3,gG.x,acc[0]); acc[1]=ffma2(W3,gG.y,acc[1]);
    acc[2]=ffma2(W3,gH.x,acc[2]); acc[3]=ffma2(W3,gH.y,acc[3]);
  }
  float a0,a1,a2,a3,a4,a5,a6,a7;
  unpack2(acc[0],a0,a1); unpack2(acc[1],a2,a3);
  unpack2(acc[2],a4,a5); unpack2(acc[3],a6,a7);
  float* yr = d_yrawp + (((size_t)(ich*4+conv)*NC + t)*NB + b)*NK;
  ((float4*)yr)[0] = make_float4(a0,a1,a2,a3);
  ((float4*)yr)[1] = make_float4(a4,a5,a6,a7);
}

// ---------------- kE2: sum i-chunk partials + BN(relu) over (B,K) ----------------
__global__ void __launch_bounds__(128) kE2(
    const float* g0,const float* b0, const float* g1,const float* b1,
    const float* g2,const float* b2, const float* g3,const float* b3){
  int o = blockIdx.x, conv = blockIdx.y, t = threadIdx.x;
  const float *gg, *bb;
  if(conv==0){gg=g0;bb=b0;} else if(conv==1){gg=g1;bb=b1;}
  else if(conv==2){gg=g2;bb=b2;} else {gg=g3;bb=b3;}
  __shared__ float sc[8];
  float v = 0.f;
  #pragma unroll
  for(int ich=0;ich<4;ich++)
    v += d_yrawp[((size_t)(ich*4+conv)*NC + o)*NB*NK + t];
  float su = blockSum(v, sc);
  float sq = blockSum(v*v, sc);
  float mean = su*(1.f/128.f);
  float var  = sq*(1.f/128.f) - mean*mean;
  float y = gg[o]*(v-mean)*rsqrtf(var+1e-5f) + bb[o];
  int b = t>>3, k = t&7;
  d_y4[((size_t)(conv*NB+b)*NC + o)*NK + k] = fmaxf(y, 0.f);
}

// ---------------- kF: mutual correlation + 2x cascade GCN + conv fold + BN stats ----------------
__global__ void __launch_bounds__(256) kF(
    const float* t2r_g1, const float* t2r_g2, const float* r2t_g1, const float* r2t_g2){
  int b = blockIdx.x, s = blockIdx.y, t = threadIdx.x;
  const float* W1  = s ? r2t_g1 : t2r_g1;
  const float* W2  = s ? r2t_g2 : t2r_g2;
  const float* cwT = d_cwT + (size_t)s*NC*NC;
  int c1 = s ? 0 : 2;
  __shared__ __align__(16) float e[NC][NK], r1[NC][NK], r2[NC][NK], xa[NC][NK], xb[NC][NK];
  __shared__ float A[NK][NK+1];
  {
    const float* gf = d_gflat + (size_t)(s*NB+b)*2048;
    const float* y1 = d_y4 + (size_t)(c1*NB+b)*NC*NK;
    const float* y2 = d_y4 + (size_t)((c1+1)*NB+b)*NC*NK;
    float4 ea = ((const float4*)(gf + t*NK))[0], eb4 = ((const float4*)(gf + t*NK))[1];
    *(float4*)&e[t][0] = ea; *(float4*)&e[t][4] = eb4;
    float4 ya = ((const float4*)(y1 + t*NK))[0], yb4 = ((const float4*)(y1 + t*NK))[1];
    *(float4*)&r1[t][0] = ya; *(float4*)&r1[t][4] = yb4;
    float4 yc = ((const float4*)(y2 + t*NK))[0], yd = ((const float4*)(y2 + t*NK))[1];
    *(float4*)&r2[t][0] = yc; *(float4*)&r2[t][4] = yd;
  }
  __syncthreads();
  {
    int pair = t>>2, part = t&3;
    int k = pair>>3, l = pair&7;
    float acc=0.f;
    #pragma unroll 4
    for(int c=part;c<NC;c+=4) acc += e[c][k]*r1[c][l];
    acc += __shfl_down_sync(0xffffffffu, acc, 1);
    acc += __shfl_down_sync(0xffffffffu, acc, 2);
    if(part==0) A[k][l] = acc;
  }
  __syncthreads();
  if(t<NK){
    float mx=A[t][0];
    #pragma unroll
    for(int l=1;l<NK;l++) mx = fmaxf(mx, A[t][l]);
    float sm=0.f, ee[NK];
    #pragma unroll
    for(int l=0;l<NK;l++){ ee[l]=expf(A[t][l]-mx); sm+=ee[l]; }
    #pragma unroll
    for(int l=0;l<NK;l++) A[t][l] = ee[l]/sm;
  }
  __syncthreads();
  {
    float rr[NK];
    float4 ra = *(float4*)&r2[t][0], rb = *(float4*)&r2[t][4];
    rr[0]=ra.x; rr[1]=ra.y; rr[2]=ra.z; rr[3]=ra.w;
    rr[4]=rb.x; rr[5]=rb.y; rr[6]=rb.z; rr[7]=rb.w;
    #pragma unroll
    for(int k=0;k<NK;k++){
      float m=0.f;
      #pragma unroll
      for(int l=0;l<NK;l++) m += A[k][l]*rr[l];
      xa[t][k] = e[t][k] + m;
    }
  }
  __syncthreads();
  for(int it=0; it<2; it++){
    float (*xin)[NK]  = it ? xb : xa;
    float (*xout)[NK] = it ? xa : xb;
    const float* W = it ? W2 : W1;
    {
      int pair=t>>2, part=t&3, k=pair>>3, l=pair&7;
      float acc=0.f;
      #pragma unroll 4
      for(int c=part;c<NC;c+=4) acc += xin[c][k]*xin[c][l];
      acc += __shfl_down_sync(0xffffffffu, acc, 1);
      acc += __shfl_down_sync(0xffffffffu, acc, 2);
      if(part==0) A[k][l]=acc;
    }
    __syncthreads();
    if(t<NK){
      float mx=A[t][0];
      #pragma unroll
      for(int l=1;l<NK;l++) mx=fmaxf(mx,A[t][l]);
      float sm=0.f, ee[NK];
      #pragma unroll
      for(int l=0;l<NK;l++){ ee[l]=expf(A[t][l]-mx); sm+=ee[l]; }
      #pragma unroll
      for(int l=0;l<NK;l++) A[t][l]=ee[l]/sm;
    }
    __syncthreads();
    float acc[NK];
    #pragma unroll
    for(int l=0;l<NK;l++) acc[l]=0.f;
    #pragma unroll 8
    for(int i=0;i<NC;i++){
      float w = W[i*NC + t];
      float4 xA = *(float4*)&xin[i][0], xB = *(float4*)&xin[i][4];
      acc[0]+=xA.x*w; acc[1]+=xA.y*w; acc[2]+=xA.z*w; acc[3]+=xA.w*w;
      acc[4]+=xB.x*w; acc[5]+=xB.y*w; acc[6]+=xB.z*w; acc[7]+=xB.w*w;
    }
    bool last = (it==1);
    #pragma unroll
    for(int k=0;k<NK;k++){
      float v=0.f;
      #pragma unroll
      for(int l=0;l<NK;l++) v += A[k][l]*acc[l];
      xout[t][k] = last ? fmaxf(v,0.f) : v;
    }
    __syncthreads();
  }
  float ce[NK];
  #pragma unroll
  for(int k=0;k<NK;k++) ce[k]=0.f;
  #pragma unroll 8
  for(int i=0;i<NC;i++){
    float w = cwT[i*NC + t];
    float4 xA = *(float4*)&xa[i][0], xB = *(float4*)&xa[i][4];
    ce[0]+=xA.x*w; ce[1]+=xA.y*w; ce[2]+=xA.z*w; ce[3]+=xA.w*w;
    ce[4]+=xB.x*w; ce[5]+=xB.y*w; ce[6]+=xB.z*w; ce[7]+=xB.w*w;
  }
  const float* sb = d_s  + (s*NB+b)*NK;
  const float* S2 = d_S2 + (s*NB+b)*64;
  float mp=0.f, vp=0.f;
  #pragma unroll
  for(int k=0;k<NK;k++) mp += ce[k]*sb[k];
  #pragma unroll
  for(int k=0;k<NK;k++)
    #pragma unroll
    for(int l=0;l<NK;l++) vp += ce[k]*ce[l]*S2[k*8+l];
  d_mpart[(s*NB+b)*NC + t] = mp;
  d_vpart[(s*NB+b)*NC + t] = vp;
  float* cep = d_ce + ((size_t)(s*NB+b)*NC + t)*NK;
  ((float4*)cep)[0] = make_float4(ce[0],ce[1],ce[2],ce[3]);
  ((float4*)cep)[1] = make_float4(ce[4],ce[5],ce[6],ce[7]);
}

// ---------------- kH: BN-fold + out = gate*x + relu(alpha*((ce.ag)/g) + beta) ----------------
__global__ void __launch_bounds__(256) kH(const float* rgb, const float* tt, float* out,
      const float* t2r_g, const float* t2r_b, const float* r2t_g, const float* r2t_b){
  int chunk = blockIdx.x, b = blockIdx.y;
  int s = blockIdx.z >> 2, cq = blockIdx.z & 3;
  int t = threadIdx.x;
  __shared__ u64 cesd[64][NK];
  __shared__ float2 ab[64];
  int n0 = chunk*1024;
  if(t<64){
    int c = cq*64 + t;
    float ms=0.f, vs=0.f;
    #pragma unroll
    for(int b2=0;b2<NB;b2++){
      ms += d_mpart[(s*NB+b2)*NC + c];
      vs += d_vpart[(s*NB+b2)*NC + c];
    }
    float mean = ms * (1.f/65536.f);
    float var  = vs * (1.f/65536.f) - mean*mean;
    float gg = s ? r2t_g[c] : t2r_g[c];
    float bv = s ? r2t_b[c] : t2r_b[c];
    float al = gg*rsqrtf(var + 1e-5f);
    ab[t] = make_float2(al, bv - al*mean);
  }
  for(int idx=t; idx<64*NK; idx+=256){
    int cl = idx>>3, k = idx&7;
    float cv = d_ce[((size_t)(s*NB+b)*NC + cq*64+cl)*NK + k];
    cesd[cl][k] = pack2(cv, cv);
  }
  const float* agp = d_ag + (size_t)(s*NB+b)*NK*NN + n0;
  u64 avlo[NK], avhi[NK];
  float4 gv;
  {
    #pragma unroll
    for(int k=0;k<NK;k++){
      float4 a4 = ((const float4*)(agp + (size_t)k*NN))[t];
      avlo[k] = pack2(a4.x, a4.y);
      avhi[k] = pack2(a4.z, a4.w);
    }
    gv = ((const float4*)(d_gate + (size_t)(s*NB+b)*NN + n0))[t];
  }
  float4 ivg = make_float4(__frcp_rn(gv.x), __frcp_rn(gv.y), __frcp_rn(gv.z), __frcp_rn(gv.w));
  __syncthreads();
  const float* xp = (s ? tt : rgb) + (size_t)b*NC*NN + n0;
  float* op = out + (size_t)s*HALF_OUT + (size_t)b*NC*NN + n0;
  #pragma unroll 2
  for(int cl=0; cl<64; cl++){
    size_t coff = (size_t)(cq*64 + cl)*NN;
    float4 xv = ((const float4*)(xp + coff))[t];
    u64 p01 = pack2(0.f,0.f), p23 = pack2(0.f,0.f);
    #pragma unroll
    for(int k=0;k<NK;k++){
      u64 cd = cesd[cl][k];
      p01 = ffma2(avlo[k], cd, p01);
      p23 = ffma2(avhi[k], cd, p23);
    }
    float px_,py_,pz_,pw_;
    unpack2(p01,px_,py_); unpack2(p23,pz_,pw_);
    float2 abv = ab[cl];
    float4 o4;
    o4.x = gv.x*xv.x + fmaxf(abv.x*(px_*ivg.x) + abv.y, 0.f);
    o4.y = gv.y*xv.y + fmaxf(abv.x*(py_*ivg.y) + abv.y, 0.f);
    o4.z = gv.z*xv.z + fmaxf(abv.x*(pz_*ivg.z) + abv.y, 0.f);
    o4.w = gv.w*xv.w + fmaxf(abv.x*(pw_*ivg.w) + abv.y, 0.f);
    ((float4*)(op + coff))[t] = o4;
  }
}

// ---------------- launch ----------------
extern "C" void kernel_launch(void* const* d_in, const int* in_sizes, int n_in,
                              void* d_out, int out_size){
  (void)in_sizes; (void)n_in; (void)out_size;
  const float* rgb    = (const float*)d_in[0];
  const float* tt     = (const float*)d_in[1];
  const float* edger  = (const float*)d_in[2];
  const float* edget  = (const float*)d_in[3];
  const float* pred_w = (const float*)d_in[4];
  const float* pred_b = (const float*)d_in[5];
  const float* rgb_anchor=(const float*)d_in[6];
  const float* rgb_sigma =(const float*)d_in[7];
  const float* t_anchor  =(const float*)d_in[8];
  const float* t_sigma   =(const float*)d_in[9];
  const float* rgb_c1_w=(const float*)d_in[10]; const float* rgb_c1_g=(const float*)d_in[11]; const float* rgb_c1_b=(const float*)d_in[12];
  const float* rgb_c2_w=(const float*)d_in[13]; const float* rgb_c2_g=(const float*)d_in[14]; const float* rgb_c2_b=(const float*)d_in[15];
  const float* t_c1_w  =(const float*)d_in[16]; const float* t_c1_g  =(const float*)d_in[17]; const float* t_c1_b  =(const float*)d_in[18];
  const float* t_c2_w  =(const float*)d_in[19]; const float* t_c2_g  =(const float*)d_in[20]; const float* t_c2_b  =(const float*)d_in[21];
  const float* t2r_conv_w=(const float*)d_in[22]; const float* t2r_conv_g=(const float*)d_in[23]; const float* t2r_conv_b=(const float*)d_in[24];
  const float* r2t_conv_w=(const float*)d_in[25]; const float* r2t_conv_g=(const float*)d_in[26]; const float* r2t_conv_b=(const float*)d_in[27];
  const float* t2r_g1=(const float*)d_in[28]; const float* t2r_g2=(const float*)d_in[29];
  const float* r2t_g1=(const float*)d_in[30]; const float* r2t_g2=(const float*)d_in[31];
  float* out = (float*)d_out;

  kI <<<784, NC>>>(rgb_anchor, rgb_sigma, t_anchor, t_sigma, t2r_conv_w, r2t_conv_w,
                   rgb_c1_w, rgb_c2_w, t_c1_w, t_c2_w);
  kBC<<<dim3(16,NB,2), 128>>>(rgb, tt, edger, edget, pred_w, pred_b);
  kD <<<dim3(NB,2), 256>>>(rgb_anchor, rgb_sigma, t_anchor, t_sigma);
  kE1<<<dim3(NB,4,4), 256>>>();
  kE2<<<dim3(NC,4), 128>>>(rgb_c1_g,rgb_c1_b, rgb_c2_g,rgb_c2_b,
                           t_c1_g,t_c1_b, t_c2_g,t_c2_b);
  kF <<<dim3(NB,2), 256>>>(t2r_g1, t2r_g2, r2t_g1, r2t_g2);
  kH <<<dim3(4,NB,8), 256>>>(rgb, tt, out, t2r_conv_g, t2r_conv_b, r2t_conv_g, r2t_conv_b);
}

// round 17
// speedup vs baseline: 1.2249x; 1.0220x over previous
#include <cuda_runtime.h>
#include <math.h>

#define NB 16
#define NC 256
#define NN 4096
#define NK 8
#define HALF_OUT (NB*NC*NN)

typedef unsigned long long u64;

// ---------------- device scratch ----------------
__device__ float  d_gate  [2*NB*NN];
__device__ float  d_ag    [2*NB*NK*NN];
__device__ float  d_s     [2*NB*NK];
__device__ float  d_S2    [2*NB*NK*NK];
__device__ float  d_wxp   [16*2*NB*NK*NC];    // per-256px-chunk partial wx
__device__ float  d_sS2p  [2*NB*16*44];       // per-chunk partial s/S2
__device__ float  d_gflat [2*NB*NK*NC];
__device__ float  d_y4    [4*NB*NC*NK];
__device__ float  d_yrawp [4*4*NC*NB*NK];     // per-ichunk partial conv outputs
__device__ float  d_ce    [2*NB*NC*NK];
__device__ float2 d_pre   [2*NK*NC];
__device__ float  d_ck    [2*NK];
__device__ float  d_cwT   [2*NC*NC];
__device__ float4 d_wP4   [4*64*256];         // packed graph-conv weights
__device__ float  d_mpart [2*NB*NC];
__device__ float  d_vpart [2*NB*NC];

// ---------------- helpers ----------------
__device__ __forceinline__ float sigmoidf_(float x){ return 1.f/(1.f+expf(-x)); }

__device__ __forceinline__ u64 pack2(float x, float y){
  u64 r; asm("mov.b64 %0,{%1,%2};" : "=l"(r) : "f"(x), "f"(y)); return r;
}
__device__ __forceinline__ void unpack2(u64 v, float& x, float& y){
  asm("mov.b64 {%0,%1},%2;" : "=f"(x), "=f"(y) : "l"(v));
}
__device__ __forceinline__ u64 ffma2(u64 a, u64 b, u64 c){
  u64 d; asm("fma.rn.f32x2 %0,%1,%2,%3;" : "=l"(d) : "l"(a), "l"(b), "l"(c)); return d;
}

__device__ __forceinline__ float warpSum(float v){
  #pragma unroll
  for(int o=16;o>0;o>>=1) v += __shfl_xor_sync(0xffffffffu, v, o);
  return v;
}
__device__ float blockSum(float v, float* scratch){
  int lane = threadIdx.x & 31, w = threadIdx.x >> 5;
  int nw = blockDim.x >> 5;
  v = warpSum(v);
  if(lane==0) scratch[w]=v;
  __syncthreads();
  float r = (threadIdx.x < nw) ? scratch[threadIdx.x] : 0.f;
  if(w==0) r = warpSum(r);
  if(threadIdx.x==0) scratch[0]=r;
  __syncthreads();
  r = scratch[0];
  __syncthreads();
  return r;
}

// ---------------- kI: anchor coeffs + cw transpose + graph-conv W packing ----------------
__global__ void kI(const float* rgb_anchor, const float* rgb_sigma,
                   const float* t_anchor,  const float* t_sigma,
                   const float* t2r_w, const float* r2t_w,
                   const float* w0, const float* w1, const float* w2, const float* w3){
  int bid = blockIdx.x, t = threadIdx.x;
  if(bid < 16){
    int s = bid>>3, k = bid&7;
    const float* anc = s ? t_anchor : rgb_anchor;
    const float* sig = s ? t_sigma  : rgb_sigma;
    float sg  = sigmoidf_(sig[k*NC+t]);
    float is2 = 1.f/(sg*sg);
    float a   = anc[k*NC+t];
    d_pre[(s*NK+k)*NC+t] = make_float2(is2, 2.f*a*is2);
    __shared__ float sc[8];
    float ck = blockSum(a*a*is2, sc);
    if(t==0) d_ck[s*NK+k] = ck;
  } else if(bid < 528){
    int r = bid-16, s = r>>8, o = r&255;
    const float* w = s ? r2t_w : t2r_w;
    d_cwT[(size_t)s*NC*NC + t*NC + o] = w[o*NC + t];
  } else {
    int r = bid-528;                  // 0..255
    int conv = r>>6, i4 = r&63;
    const float* w = (conv==0)?w0 : (conv==1)?w1 : (conv==2)?w2 : w3;
    int o = t;
    d_wP4[((size_t)conv*64 + i4)*256 + o] = make_float4(
        w[o*NC + 4*i4], w[o*NC + 4*i4 + 1], w[o*NC + 4*i4 + 2], w[o*NC + 4*i4 + 3]);
  }
}

// ---------------- kBC: gate + q + softmax + wx partials (128 thr, 256-px chunks) ----------------
__global__ void __launch_bounds__(128) kBC(const float* rgb, const float* tt,
      const float* edger, const float* edget, const float* pred_w, const float* pred_b){
  int chunk = blockIdx.x, b = blockIdx.y, s = blockIdx.z;
  int t = threadIdx.x;                          // 0..127
  __shared__ u64 agsp[4][256];                  // packed (k-pair) assign*gate, px-major, 8 KB
  __shared__ __align__(16) char ubuf[16384];    // predup (16K) then red (9.2K)
  __shared__ float pw[NC];
  __shared__ float cks[NK];
  __shared__ float part[44][4];
  ulonglong2 (*predup)[256] = (ulonglong2(*)[256])ubuf;
  float (*red)[4][9] = (float(*)[4][9])ubuf;    // [64][4][9]

  pw[t] = pred_w[t]; pw[t+128] = pred_w[t+128];
  for(int idx=t; idx<4*NC; idx+=128){
    int kp = idx >> 8, c = idx & 255;
    float2 pa = d_pre[s*2048 + (2*kp  )*NC + c];
    float2 pb = d_pre[s*2048 + (2*kp+1)*NC + c];
    ulonglong2 v;
    v.x = pack2(pa.x, pb.x);
    v.y = pack2(-pa.y, -pb.y);
    predup[kp][c] = v;
  }
  if(t<NK) cks[t] = d_ck[s*NK+t];
  __syncthreads();

  int n0 = chunk*256;
  const float* ep = (s ? edget : edger) + (size_t)b*NC*NN + n0;
  const float* xp = (s ? tt    : rgb  ) + (size_t)b*NC*NN + n0;

  // ---- gate ----
  u64 gaA = pack2(0.f,0.f), gaB = pack2(0.f,0.f);
  {
    const float2* ep2 = (const float2*)ep;
    #pragma unroll 4
    for(int c=0;c<NC;c+=2){
      float2 e0 = ep2[(size_t)(c  )*(NN/2) + t];
      float2 e1 = ep2[(size_t)(c+1)*(NN/2) + t];
      gaA = ffma2(pack2(pw[c],pw[c]),     pack2(e0.x,e0.y), gaA);
      gaB = ffma2(pack2(pw[c+1],pw[c+1]), pack2(e1.x,e1.y), gaB);
    }
  }
  float ga0,ga1, gb0,gb1;
  unpack2(gaA,ga0,ga1); unpack2(gaB,gb0,gb1);
  float pb = pred_b[0];
  float g0 = sigmoidf_(ga0+gb0+pb), g1 = sigmoidf_(ga1+gb1+pb);

  // ---- q distances ----
  u64 qaS[4], qaL[4], qbS[4], qbL[4];
  #pragma unroll
  for(int kp=0;kp<4;kp++){
    qaS[kp]=pack2(cks[2*kp],cks[2*kp+1]); qbS[kp]=qaS[kp];
    qaL[kp]=pack2(0.f,0.f); qbL[kp]=pack2(0.f,0.f);
  }
  {
    const float2* xp2 = (const float2*)xp;
    #pragma unroll 4
    for(int c=0;c<NC;c++){
      float2 xv = xp2[(size_t)c*(NN/2)+t];
      float x0 = xv.x*g0, x1 = xv.y*g1;
      float x0s = x0*x0,  x1s = x1*x1;
      u64 X0 = pack2(x0,x0),   X1 = pack2(x1,x1);
      u64 X0s= pack2(x0s,x0s), X1s= pack2(x1s,x1s);
      #pragma unroll
      for(int kp=0;kp<4;kp++){
        ulonglong2 pd = predup[kp][c];
        qaS[kp] = ffma2(X0s, pd.x, qaS[kp]);
        qaL[kp] = ffma2(X0,  pd.y, qaL[kp]);
        qbS[kp] = ffma2(X1s, pd.x, qbS[kp]);
        qbL[kp] = ffma2(X1,  pd.y, qbL[kp]);
      }
    }
  }
  float q0[NK], q1[NK];
  #pragma unroll
  for(int kp=0;kp<4;kp++){
    float sA,sB,lA,lB;
    unpack2(qaS[kp],sA,sB); unpack2(qaL[kp],lA,lB);
    q0[2*kp]=sA+lA; q0[2*kp+1]=sB+lB;
    unpack2(qbS[kp],sA,sB); unpack2(qbL[kp],lA,lB);
    q1[2*kp]=sA+lA; q1[2*kp+1]=sB+lB;
  }

  // ---- softmax ----
  float a0[NK], a1[NK];
  {
    float mx0=-0.5f*q0[0], mx1=-0.5f*q1[0];
    #pragma unroll
    for(int k=1;k<NK;k++){ mx0=fmaxf(mx0,-0.5f*q0[k]); mx1=fmaxf(mx1,-0.5f*q1[k]); }
    float s0=0.f, s1=0.f;
    #pragma unroll
    for(int k=0;k<NK;k++){
      a0[k]=expf(-0.5f*q0[k]-mx0); s0+=a0[k];
      a1[k]=expf(-0.5f*q1[k]-mx1); s1+=a1[k];
    }
    float i0=1.f/s0, i1=1.f/s1;
    #pragma unroll
    for(int k=0;k<NK;k++){ a0[k]*=i0; a1[k]*=i1; }
  }
  // ---- write ag + gate; stage packed agsp (px 2t, 2t+1) ----
  {
    float a0g[NK], a1g[NK];
    #pragma unroll
    for(int k=0;k<NK;k++){ a0g[k]=a0[k]*g0; a1g[k]=a1[k]*g1; }
    float* agp = d_ag + (size_t)(s*NB+b)*NK*NN + n0;
    #pragma unroll
    for(int k=0;k<NK;k++)
      ((float2*)(agp + (size_t)k*NN))[t] = make_float2(a0g[k], a1g[k]);
    ((float2*)(d_gate + (size_t)(s*NB+b)*NN + n0))[t] = make_float2(g0, g1);
    #pragma unroll
    for(int kp=0;kp<4;kp++){
      ulonglong2 v;
      v.x = pack2(a0g[2*kp], a0g[2*kp+1]);    // pixel 2t
      v.y = pack2(a1g[2*kp], a1g[2*kp+1]);    // pixel 2t+1
      ((ulonglong2*)agsp[kp])[t] = v;
    }
  }
  // ---- s/S2 partials ----
  {
    int lane = t&31, w = t>>5;
    #pragma unroll
    for(int k=0;k<NK;k++){
      float v = warpSum(a0[k]+a1[k]);
      if(lane==0) part[k][w]=v;
    }
    int idx=8;
    #pragma unroll
    for(int k=0;k<NK;k++)
      #pragma unroll
      for(int l=k;l<NK;l++){
        float v = warpSum(a0[k]*a0[l] + a1[k]*a1[l]);
        if(lane==0) part[idx][w]=v;
        idx++;
      }
  }
  __syncthreads();
  if(t<44){
    float sv=0.f;
    #pragma unroll
    for(int p=0;p<4;p++) sv += part[t][p];
    d_sS2p[((s*NB+b)*16+chunk)*44 + t] = sv;
  }

  // ---- phase 2: wx partials from L2-resident x ----
  int cl = t>>2, nsub = t&3;                    // cl: 0..31, nsub: 0..3
  for(int cg=0; cg<4; cg++){
    int c0 = cg*64 + cl, c1 = c0 + 32;
    const float4* x0p = (const float4*)(xp + (size_t)c0*NN);
    const float4* x1p = (const float4*)(xp + (size_t)c1*NN);
    u64 acc0[4], acc1[4];
    #pragma unroll
    for(int kp=0;kp<4;kp++){ acc0[kp]=pack2(0.f,0.f); acc1[kp]=acc0[kp]; }
    #pragma unroll 4
    for(int i=0;i<16;i++){
      int j = nsub + i*4;                       // j < 64 (256px / 4)
      float4 xv0 = x0p[j];
      float4 xv1 = x1p[j];
      u64 P0x=pack2(xv0.x,xv0.x), P0y=pack2(xv0.y,xv0.y), P0z=pack2(xv0.z,xv0.z), P0w=pack2(xv0.w,xv0.w);
      u64 P1x=pack2(xv1.x,xv1.x), P1y=pack2(xv1.y,xv1.y), P1z=pack2(xv1.z,xv1.z), P1w=pack2(xv1.w,xv1.w);
      #pragma unroll
      for(int kp=0;kp<4;kp++){
        ulonglong2 apA = ((ulonglong2*)agsp[kp])[2*j];     // px 4j, 4j+1
        ulonglong2 apB = ((ulonglong2*)agsp[kp])[2*j+1];   // px 4j+2, 4j+3
        acc0[kp] = ffma2(P0x, apA.x, acc0[kp]);
        acc0[kp] = ffma2(P0y, apA.y, acc0[kp]);
        acc0[kp] = ffma2(P0z, apB.x, acc0[kp]);
        acc0[kp] = ffma2(P0w, apB.y, acc0[kp]);
        acc1[kp] = ffma2(P1x, apA.x, acc1[kp]);
        acc1[kp] = ffma2(P1y, apA.y, acc1[kp]);
        acc1[kp] = ffma2(P1z, apB.x, acc1[kp]);
        acc1[kp] = ffma2(P1w, apB.y, acc1[kp]);
      }
    }
    __syncthreads();
    #pragma unroll
    for(int kp=0;kp<4;kp++){
      float r0,r1;
      unpack2(acc0[kp],r0,r1); red[cl][nsub][2*kp]=r0; red[cl][nsub][2*kp+1]=r1;
      unpack2(acc1[kp],r0,r1); red[cl+32][nsub][2*kp]=r0; red[cl+32][nsub][2*kp+1]=r1;
    }
    __syncthreads();
    float* wout = d_wxp + ((size_t)(chunk*(2*NB) + s*NB+b))*NK*NC;
    for(int r=t; r<512; r+=128){
      int cc = r>>3, k2 = r&7;
      float sum = 0.f;
      #pragma unroll
      for(int p=0;p<4;p++) sum += red[cc][p][k2];
      wout[(size_t)k2*NC + cg*64 + cc] = sum;
    }
    __syncthreads();
  }
}

// ---------------- kD: reduce partials, nodes -> l2norms -> gflat ----------------
__global__ void __launch_bounds__(256) kD(const float* rgb_anchor, const float* rgb_sigma,
                   const float* t_anchor,  const float* t_sigma){
  int b = blockIdx.x, s = blockIdx.y, t = threadIdx.x;
  __shared__ float sc[8];
  __shared__ float s_sh[NK];
  __shared__ float part[NK][8];
  __shared__ float nks[NK];
  if(t<44){
    float sv=0.f;
    #pragma unroll
    for(int ch=0;ch<16;ch++) sv += d_sS2p[((s*NB+b)*16+ch)*44 + t];
    if(t<8){ d_s[(s*NB+b)*8 + t] = sv; s_sh[t] = sv; }
    else {
      int p=t-8, k=0;
      while(p >= NK-k){ p -= NK-k; k++; }
      int l = k+p;
      d_S2[(s*NB+b)*64 + k*8 + l] = sv;
      d_S2[(s*NB+b)*64 + l*8 + k] = sv;
    }
  }
  __syncthreads();
  const float* anc = s ? t_anchor : rgb_anchor;
  const float* sig = s ? t_sigma  : rgb_sigma;
  float val[NK];
  #pragma unroll
  for(int k=0;k<NK;k++){
    float wxv = 0.f;
    #pragma unroll
    for(int ch=0;ch<16;ch++)
      wxv += d_wxp[((size_t)(ch*(2*NB) + s*NB+b)*NK + k)*NC + t];
    float sv  = s_sh[k];
    float sg  = sigmoidf_(sig[k*NC+t]);
    val[k] = (wxv - sv*anc[k*NC+t]) / sg / (sv + 1e-9f);
  }
  int lane = t&31, w = t>>5;
  #pragma unroll
  for(int k=0;k<NK;k++){
    float v = warpSum(val[k]*val[k]);
    if(lane==0) part[k][w]=v;
  }
  __syncthreads();
  if(t<NK){
    float sv=0.f;
    #pragma unroll
    for(int p=0;p<8;p++) sv += part[t][p];
    nks[t] = fmaxf(sqrtf(sv), 1e-12f);
  }
  __syncthreads();
  float gss = 0.f;
  #pragma unroll
  for(int k=0;k<NK;k++){ val[k] = val[k]/nks[k]; gss += val[k]*val[k]; }
  float G = blockSum(gss, sc);
  float gn = fmaxf(sqrtf(G), 1e-12f);
  float* gf = d_gflat + (size_t)(s*NB+b)*2048;
  #pragma unroll
  for(int k=0;k<NK;k++) gf[k*NC+t] = val[k]/gn;
}

// ---------------- kE1: 4 graph convs, pre-BN, i-split into 4 chunks ----------------
__global__ void __launch_bounds__(256) kE1(){
  int b = blockIdx.x, conv = blockIdx.y, ich = blockIdx.z;
  int t = threadIdx.x;
  int side = conv>>1;
  __shared__ __align__(16) float gfs[512];
  {
    const float4* src = (const float4*)(d_gflat + (size_t)(side*NB+b)*2048 + ich*512);
    if(t<128) ((float4*)gfs)[t] = src[t];
  }
  __syncthreads();
  const float4* WP = d_wP4 + (size_t)conv*64*256 + (size_t)ich*16*256;
  u64 acc[4];
  #pragma unroll
  for(int kp=0;kp<4;kp++) acc[kp] = pack2(0.f,0.f);
  #pragma unroll
  for(int i4=0;i4<16;i4++){
    float4 w4 = WP[i4*256 + t];
    const ulonglong2* gp = ((const ulonglong2*)gfs) + i4*8;
    ulonglong2 gA = gp[0], gB = gp[1];
    ulonglong2 gC = gp[2], gD = gp[3];
    ulonglong2 gE = gp[4], gF = gp[5];
    ulonglong2 gG = gp[6], gH = gp[7];
    u64 W0=pack2(w4.x,w4.x), W1=pack2(w4.y,w4.y), W2=pack2(w4.z,w4.z), W3=pack2(w4.w,w4.w);
    acc[0]=ffma2(W0,gA.x,acc[0]); acc[1]=ffma2(W0,gA.y,acc[1]);
    acc[2]=ffma2(W0,gB.x,acc[2]); acc[3]=ffma2(W0,gB.y,acc[3]);
    acc[0]=ffma2(W1,gC.x,acc[0]); acc[1]=ffma2(W1,gC.y,acc[1]);
    acc[2]=ffma2(W1,gD.x,acc[2]); acc[3]=ffma2(W1,gD.y,acc[3]);
    acc[0]=ffma2(W2,gE.x,acc[0]); acc[1]=ffma2(W2,gE.y,acc[1]);
    acc[2]=ffma2(W2,gF.x,acc[2]); acc[3]=ffma2(W2,gF.y,acc[3]);
    acc[0]=ffma2(W3,gG.x,acc[0]); acc[1]=ffma2(W3,gG.y,acc[1]);
    acc[2]=ffma2(W3,gH.x,acc[2]); acc[3]=ffma2(W3,gH.y,acc[3]);
  }
  float a0,a1,a2,a3,a4,a5,a6,a7;
  unpack2(acc[0],a0,a1); unpack2(acc[1],a2,a3);
  unpack2(acc[2],a4,a5); unpack2(acc[3],a6,a7);
  float* yr = d_yrawp + (((size_t)(ich*4+conv)*NC + t)*NB + b)*NK;
  ((float4*)yr)[0] = make_float4(a0,a1,a2,a3);
  ((float4*)yr)[1] = make_float4(a4,a5,a6,a7);
}

// ---------------- kE2: sum i-chunk partials + BN(relu) over (B,K) ----------------
__global__ void __launch_bounds__(128) kE2(
    const float* g0,const float* b0, const float* g1,const float* b1,
    const float* g2,const float* b2, const float* g3,const float* b3){
  int o = blockIdx.x, conv = blockIdx.y, t = threadIdx.x;
  const float *gg, *bb;
  if(conv==0){gg=g0;bb=b0;} else if(conv==1){gg=g1;bb=b1;}
  else if(conv==2){gg=g2;bb=b2;} else {gg=g3;bb=b3;}
  __shared__ float sc[8];
  float v = 0.f;
  #pragma unroll
  for(int ich=0;ich<4;ich++)
    v += d_yrawp[((size_t)(ich*4+conv)*NC + o)*NB*NK + t];
  float su = blockSum(v, sc);
  float sq = blockSum(v*v, sc);
  float mean = su*(1.f/128.f);
  float var  = sq*(1.f/128.f) - mean*mean;
  float y = gg[o]*(v-mean)*rsqrtf(var+1e-5f) + bb[o];
  int b = t>>3, k = t&7;
  d_y4[((size_t)(conv*NB+b)*NC + o)*NK + k] = fmaxf(y, 0.f);
}

// ---------------- kF: mutual correlation + 2x cascade GCN + conv fold + BN stats ----------------
__global__ void __launch_bounds__(256) kF(
    const float* t2r_g1, const float* t2r_g2, const float* r2t_g1, const float* r2t_g2){
  int b = blockIdx.x, s = blockIdx.y, t = threadIdx.x;
  const float* W1  = s ? r2t_g1 : t2r_g1;
  const float* W2  = s ? r2t_g2 : t2r_g2;
  const float* cwT = d_cwT + (size_t)s*NC*NC;
  int c1 = s ? 0 : 2;
  __shared__ __align__(16) float e[NC][NK], r1[NC][NK], r2[NC][NK], xa[NC][NK], xb[NC][NK];
  __shared__ float A[NK][NK+1];
  {
    const float* gf = d_gflat + (size_t)(s*NB+b)*2048;
    const float* y1 = d_y4 + (size_t)(c1*NB+b)*NC*NK;
    const float* y2 = d_y4 + (size_t)((c1+1)*NB+b)*NC*NK;
    float4 ea = ((const float4*)(gf + t*NK))[0], eb4 = ((const float4*)(gf + t*NK))[1];
    *(float4*)&e[t][0] = ea; *(float4*)&e[t][4] = eb4;
    float4 ya = ((const float4*)(y1 + t*NK))[0], yb4 = ((const float4*)(y1 + t*NK))[1];
    *(float4*)&r1[t][0] = ya; *(float4*)&r1[t][4] = yb4;
    float4 yc = ((const float4*)(y2 + t*NK))[0], yd = ((const float4*)(y2 + t*NK))[1];
    *(float4*)&r2[t][0] = yc; *(float4*)&r2[t][4] = yd;
  }
  __syncthreads();
  {
    int pair = t>>2, part = t&3;
    int k = pair>>3, l = pair&7;
    float acc=0.f;
    #pragma unroll 4
    for(int c=part;c<NC;c+=4) acc += e[c][k]*r1[c][l];
    acc += __shfl_down_sync(0xffffffffu, acc, 1);
    acc += __shfl_down_sync(0xffffffffu, acc, 2);
    if(part==0) A[k][l] = acc;
  }
  __syncthreads();
  if(t<NK){
    float mx=A[t][0];
    #pragma unroll
    for(int l=1;l<NK;l++) mx = fmaxf(mx, A[t][l]);
    float sm=0.f, ee[NK];
    #pragma unroll
    for(int l=0;l<NK;l++){ ee[l]=expf(A[t][l]-mx); sm+=ee[l]; }
    #pragma unroll
    for(int l=0;l<NK;l++) A[t][l] = ee[l]/sm;
  }
  __syncthreads();
  {
    float rr[NK];
    float4 ra = *(float4*)&r2[t][0], rb = *(float4*)&r2[t][4];
    rr[0]=ra.x; rr[1]=ra.y; rr[2]=ra.z; rr[3]=ra.w;
    rr[4]=rb.x; rr[5]=rb.y; rr[6]=rb.z; rr[7]=rb.w;
    #pragma unroll
    for(int k=0;k<NK;k++){
      float m=0.f;
      #pragma unroll
      for(int l=0;l<NK;l++) m += A[k][l]*rr[l];
      xa[t][k] = e[t][k] + m;
    }
  }
  __syncthreads();
  for(int it=0; it<2; it++){
    float (*xin)[NK]  = it ? xb : xa;
    float (*xout)[NK] = it ? xa : xb;
    const float* W = it ? W2 : W1;
    {
      int pair=t>>2, part=t&3, k=pair>>3, l=pair&7;
      float acc=0.f;
      #pragma unroll 4
      for(int c=part;c<NC;c+=4) acc += xin[c][k]*xin[c][l];
      acc += __shfl_down_sync(0xffffffffu, acc, 1);
      acc += __shfl_down_sync(0xffffffffu, acc, 2);
      if(part==0) A[k][l]=acc;
    }
    __syncthreads();
    if(t<NK){
      float mx=A[t][0];
      #pragma unroll
      for(int l=1;l<NK;l++) mx=fmaxf(mx,A[t][l]);
      float sm=0.f, ee[NK];
      #pragma unroll
      for(int l=0;l<NK;l++){ ee[l]=expf(A[t][l]-mx); sm+=ee[l]; }
      #pragma unroll
      for(int l=0;l<NK;l++) A[t][l]=ee[l]/sm;
    }
    __syncthreads();
    float acc[NK];
    #pragma unroll
    for(int l=0;l<NK;l++) acc[l]=0.f;
    #pragma unroll 8
    for(int i=0;i<NC;i++){
      float w = W[i*NC + t];
      float4 xA = *(float4*)&xin[i][0], xB = *(float4*)&xin[i][4];
      acc[0]+=xA.x*w; acc[1]+=xA.y*w; acc[2]+=xA.z*w; acc[3]+=xA.w*w;
      acc[4]+=xB.x*w; acc[5]+=xB.y*w; acc[6]+=xB.z*w; acc[7]+=xB.w*w;
    }
    bool last = (it==1);
    #pragma unroll
    for(int k=0;k<NK;k++){
      float v=0.f;
      #pragma unroll
      for(int l=0;l<NK;l++) v += A[k][l]*acc[l];
      xout[t][k] = last ? fmaxf(v,0.f) : v;
    }
    __syncthreads();
  }
  float ce[NK];
  #pragma unroll
  for(int k=0;k<NK;k++) ce[k]=0.f;
  #pragma unroll 8
  for(int i=0;i<NC;i++){
    float w = cwT[i*NC + t];
    float4 xA = *(float4*)&xa[i][0], xB = *(float4*)&xa[i][4];
    ce[0]+=xA.x*w; ce[1]+=xA.y*w; ce[2]+=xA.z*w; ce[3]+=xA.w*w;
    ce[4]+=xB.x*w; ce[5]+=xB.y*w; ce[6]+=xB.z*w; ce[7]+=xB.w*w;
  }
  const float* sb = d_s  + (s*NB+b)*NK;
  const float* S2 = d_S2 + (s*NB+b)*64;
  float mp=0.f, vp=0.f;
  #pragma unroll
  for(int k=0;k<NK;k++) mp += ce[k]*sb[k];
  #pragma unroll
  for(int k=0;k<NK;k++)
    #pragma unroll
    for(int l=0;l<NK;l++) vp += ce[k]*ce[l]*S2[k*8+l];
  d_mpart[(s*NB+b)*NC + t] = mp;
  d_vpart[(s*NB+b)*NC + t] = vp;
  float* cep = d_ce + ((size_t)(s*NB+b)*NC + t)*NK;
  ((float4*)cep)[0] = make_float4(ce[0],ce[1],ce[2],ce[3]);
  ((float4*)cep)[1] = make_float4(ce[4],ce[5],ce[6],ce[7]);
}

// ---------------- kH: BN-fold + out = gate*x + relu(alpha*((ce.ag)/g) + beta) ----------------
// 128 threads, 512-px chunks, 64-channel quarters -> 1024 blocks
__global__ void __launch_bounds__(128) kH(const float* rgb, const float* tt, float* out,
      const float* t2r_g, const float* t2r_b, const float* r2t_g, const float* r2t_b){
  int chunk = blockIdx.x, b = blockIdx.y;
  int s = blockIdx.z >> 2, cq = blockIdx.z & 3;
  int t = threadIdx.x;                           // 0..127, 4 px each
  __shared__ u64 cesd[64][NK];
  __shared__ float2 ab[64];
  int n0 = chunk*512;
  if(t<64){
    int c = cq*64 + t;
    float ms=0.f, vs=0.f;
    #pragma unroll
    for(int b2=0;b2<NB;b2++){
      ms += d_mpart[(s*NB+b2)*NC + c];
      vs += d_vpart[(s*NB+b2)*NC + c];
    }
    float mean = ms * (1.f/65536.f);
    float var  = vs * (1.f/65536.f) - mean*mean;
    float gg = s ? r2t_g[c] : t2r_g[c];
    float bv = s ? r2t_b[c] : t2r_b[c];
    float al = gg*rsqrtf(var + 1e-5f);
    ab[t] = make_float2(al, bv - al*mean);
  }
  for(int idx=t; idx<64*NK; idx+=128){
    int cl = idx>>3, k = idx&7;
    float cv = d_ce[((size_t)(s*NB+b)*NC + cq*64+cl)*NK + k];
    cesd[cl][k] = pack2(cv, cv);
  }
  const float* agp = d_ag + (size_t)(s*NB+b)*NK*NN + n0;
  u64 avlo[NK], avhi[NK];
  float4 gv;
  {
    #pragma unroll
    for(int k=0;k<NK;k++){
      float4 a4 = ((const float4*)(agp + (size_t)k*NN))[t];
      avlo[k] = pack2(a4.x, a4.y);
      avhi[k] = pack2(a4.z, a4.w);
    }
    gv = ((const float4*)(d_gate + (size_t)(s*NB+b)*NN + n0))[t];
  }
  float4 ivg = make_float4(__frcp_rn(gv.x), __frcp_rn(gv.y), __frcp_rn(gv.z), __frcp_rn(gv.w));
  __syncthreads();
  const float* xp = (s ? tt : rgb) + (size_t)b*NC*NN + n0;
  float* op = out + (size_t)s*HALF_OUT + (size_t)b*NC*NN + n0;
  #pragma unroll 4
  for(int cl=0; cl<64; cl++){
    size_t coff = (size_t)(cq*64 + cl)*NN;
    float4 xv = ((const float4*)(xp + coff))[t];
    u64 p01 = pack2(0.f,0.f), p23 = pack2(0.f,0.f);
    #pragma unroll
    for(int k=0;k<NK;k++){
      u64 cd = cesd[cl][k];
      p01 = ffma2(avlo[k], cd, p01);
      p23 = ffma2(avhi[k], cd, p23);
    }
    float px_,py_,pz_,pw_;
    unpack2(p01,px_,py_); unpack2(p23,pz_,pw_);
    float2 abv = ab[cl];
    float4 o4;
    o4.x = gv.x*xv.x + fmaxf(abv.x*(px_*ivg.x) + abv.y, 0.f);
    o4.y = gv.y*xv.y + fmaxf(abv.x*(py_*ivg.y) + abv.y, 0.f);
    o4.z = gv.z*xv.z + fmaxf(abv.x*(pz_*ivg.z) + abv.y, 0.f);
    o4.w = gv.w*xv.w + fmaxf(abv.x*(pw_*ivg.w) + abv.y, 0.f);
    ((float4*)(op + coff))[t] = o4;
  }
}

// ---------------- launch ----------------
extern "C" void kernel_launch(void* const* d_in, const int* in_sizes, int n_in,
                              void* d_out, int out_size){
  (void)in_sizes; (void)n_in; (void)out_size;
  const float* rgb    = (const float*)d_in[0];
  const float* tt     = (const float*)d_in[1];
  const float* edger  = (const float*)d_in[2];
  const float* edget  = (const float*)d_in[3];
  const float* pred_w = (const float*)d_in[4];
  const float* pred_b = (const float*)d_in[5];
  const float* rgb_anchor=(const float*)d_in[6];
  const float* rgb_sigma =(const float*)d_in[7];
  const float* t_anchor  =(const float*)d_in[8];
  const float* t_sigma   =(const float*)d_in[9];
  const float* rgb_c1_w=(const float*)d_in[10]; const float* rgb_c1_g=(const float*)d_in[11]; const float* rgb_c1_b=(const float*)d_in[12];
  const float* rgb_c2_w=(const float*)d_in[13]; const float* rgb_c2_g=(const float*)d_in[14]; const float* rgb_c2_b=(const float*)d_in[15];
  const float* t_c1_w  =(const float*)d_in[16]; const float* t_c1_g  =(const float*)d_in[17]; const float* t_c1_b  =(const float*)d_in[18];
  const float* t_c2_w  =(const float*)d_in[19]; const float* t_c2_g  =(const float*)d_in[20]; const float* t_c2_b  =(const float*)d_in[21];
  const float* t2r_conv_w=(const float*)d_in[22]; const float* t2r_conv_g=(const float*)d_in[23]; const float* t2r_conv_b=(const float*)d_in[24];
  const float* r2t_conv_w=(const float*)d_in[25]; const float* r2t_conv_g=(const float*)d_in[26]; const float* r2t_conv_b=(const float*)d_in[27];
  const float* t2r_g1=(const float*)d_in[28]; const float* t2r_g2=(const float*)d_in[29];
  const float* r2t_g1=(const float*)d_in[30]; const float* r2t_g2=(const float*)d_in[31];
  float* out = (float*)d_out;

  kI <<<784, NC>>>(rgb_anchor, rgb_sigma, t_anchor, t_sigma, t2r_conv_w, r2t_conv_w,
                   rgb_c1_w, rgb_c2_w, t_c1_w, t_c2_w);
  kBC<<<dim3(16,NB,2), 128>>>(rgb, tt, edger, edget, pred_w, pred_b);
  kD <<<dim3(NB,2), 256>>>(rgb_anchor, rgb_sigma, t_anchor, t_sigma);
  kE1<<<dim3(NB,4,4), 256>>>();
  kE2<<<dim3(NC,4), 128>>>(rgb_c1_g,rgb_c1_b, rgb_c2_g,rgb_c2_b,
                           t_c1_g,t_c1_b, t_c2_g,t_c2_b);
  kF <<<dim3(NB,2), 256>>>(t2r_g1, t2r_g2, r2t_g1, r2t_g2);
  kH <<<dim3(8,NB,8), 128>>>(rgb, tt, out, t2r_conv_g, t2r_conv_b, r2t_conv_g, r2t_conv_b);
}